// round 1
// baseline (speedup 1.0000x reference)
#include <cuda_runtime.h>
#include <math.h>

#define S_LEN   4096
#define E_DIM   2048
#define H_NUM   16
#define D_HEAD  128
#define HD      2048
#define T_TILES 32
#define K_ANCH  8
#define TILE    128

// Scratch (device globals: no allocation allowed in kernel_launch)
__device__ float g_q[S_LEN * HD];
__device__ float g_k[S_LEN * HD];
__device__ float g_v[S_LEN * HD];
__device__ float g_attn[S_LEN * HD];

// ---------------------------------------------------------------------------
// SGEMM: C[M,N] = A[M,K] * B[K,N], fp32, 128x128 block, 8x8 micro, 256 threads
// M,N multiples of 128; K multiple of 16. All true here (4096/2048/2048).
// ---------------------------------------------------------------------------
#define BM 128
#define BN 128
#define BKK 16

__global__ __launch_bounds__(256) void sgemm_kernel(
    const float* __restrict__ A, const float* __restrict__ B,
    float* __restrict__ C, int M, int N, int Kd)
{
    __shared__ float As[BKK][BM + 4];   // transposed A tile: As[k][m]
    __shared__ float Bs[BKK][BN];       // natural B tile:    Bs[k][n]

    const int tid  = threadIdx.x;
    const int tr   = tid >> 4;          // 0..15 (row group)
    const int tc   = tid & 15;          // 0..15 (col group)
    const int mBase = blockIdx.y * BM;
    const int nBase = blockIdx.x * BN;

    const int aRow  = tid >> 2;         // 0..63
    const int aCol  = (tid & 3) << 2;   // 0,4,8,12
    const int bRow  = tid >> 5;         // 0..7
    const int bCol  = (tid & 31) << 2;  // 0..124

    float acc[8][8];
#pragma unroll
    for (int i = 0; i < 8; i++)
#pragma unroll
        for (int j = 0; j < 8; j++) acc[i][j] = 0.f;

    for (int k0 = 0; k0 < Kd; k0 += BKK) {
        // Load A tile (transpose into As[k][m])
#pragma unroll
        for (int i = 0; i < 2; i++) {
            float4 a = *(const float4*)(A + (mBase + aRow + i * 64) * Kd + k0 + aCol);
            As[aCol + 0][aRow + i * 64] = a.x;
            As[aCol + 1][aRow + i * 64] = a.y;
            As[aCol + 2][aRow + i * 64] = a.z;
            As[aCol + 3][aRow + i * 64] = a.w;
        }
        // Load B tile (natural)
#pragma unroll
        for (int i = 0; i < 2; i++) {
            *(float4*)(&Bs[bRow + i * 8][bCol]) =
                *(const float4*)(B + (k0 + bRow + i * 8) * N + nBase + bCol);
        }
        __syncthreads();

#pragma unroll
        for (int k = 0; k < BKK; k++) {
            float af[8], bf[8];
            *(float4*)(af)     = *(float4*)(&As[k][tr * 8]);
            *(float4*)(af + 4) = *(float4*)(&As[k][tr * 8 + 4]);
            *(float4*)(bf)     = *(float4*)(&Bs[k][tc * 8]);
            *(float4*)(bf + 4) = *(float4*)(&Bs[k][tc * 8 + 4]);
#pragma unroll
            for (int i = 0; i < 8; i++)
#pragma unroll
                for (int j = 0; j < 8; j++)
                    acc[i][j] += af[i] * bf[j];
        }
        __syncthreads();
    }

#pragma unroll
    for (int i = 0; i < 8; i++) {
        float* cp = C + (mBase + tr * 8 + i) * N + nBase + tc * 8;
        *(float4*)(cp)     = make_float4(acc[i][0], acc[i][1], acc[i][2], acc[i][3]);
        *(float4*)(cp + 4) = make_float4(acc[i][4], acc[i][5], acc[i][6], acc[i][7]);
    }
}

// ---------------------------------------------------------------------------
// RoPE (half-split / rotate_half), applied in-place to q and k.
// One thread per (s, h, p<64) pair.
// ---------------------------------------------------------------------------
__global__ __launch_bounds__(256) void rope_kernel(
    float* __restrict__ q, float* __restrict__ k, const float* __restrict__ ang)
{
    int idx = blockIdx.x * blockDim.x + threadIdx.x;
    if (idx >= S_LEN * H_NUM * 64) return;
    int p = idx & 63;
    int h = (idx >> 6) & 15;
    int s = idx >> 10;
    float a = ang[s * 64 + p];
    float c = cosf(a), sn = sinf(a);
    int base = s * HD + h * D_HEAD;

    float q0 = q[base + p], q1 = q[base + p + 64];
    q[base + p]      = q0 * c - q1 * sn;
    q[base + p + 64] = q1 * c + q0 * sn;

    float k0 = k[base + p], k1 = k[base + p + 64];
    k[base + p]      = k0 * c - k1 * sn;
    k[base + p + 64] = k1 * c + k0 * sn;
}

// ---------------------------------------------------------------------------
// Block-sparse flash attention.
// Grid: (T_TILES, H_NUM). 256 threads. One CTA owns one (q-tile, head).
// smem: qs (natural [r][d]), kv (K transposed [d][c] then V natural [c][d]),
//       ps (natural [r][c]); pitch 132 floats; 202,752 bytes total.
// ---------------------------------------------------------------------------
#define PT 132
#define ATT_SMEM (3 * 128 * PT * 4)

__global__ __launch_bounds__(256) void attn_kernel(
    const float* __restrict__ qg, const float* __restrict__ kg,
    const float* __restrict__ vg, const int* __restrict__ anchors,
    float* __restrict__ outg)
{
    extern __shared__ float smem[];
    float* qs = smem;                 // [128][PT] natural
    float* kv = smem + 128 * PT;      // K: [d][c] transposed / V: [c][d] natural
    float* ps = smem + 2 * 128 * PT;  // [128][PT] natural (P)

    const int t   = blockIdx.x;
    const int h   = blockIdx.y;
    const int tid = threadIdx.x;
    const int ty  = tid >> 4;         // 0..15 -> query rows ty*8..ty*8+7
    const int tx  = tid & 15;         // 0..15 -> key/out cols tx*8..tx*8+7
    const float sm_scale = 0.08838834764831845f;  // 1/sqrt(128)

    // Load Q tile (natural, coalesced)
#pragma unroll
    for (int it = 0; it < 16; it++) {
        int chunk = tid + it * 256;
        int token = chunk >> 5;
        int d4    = (chunk & 31) << 2;
        *(float4*)(qs + token * PT + d4) =
            *(const float4*)(qg + (t * TILE + token) * HD + h * D_HEAD + d4);
    }

    float m_i[8], l_i[8], acc[8][8];
#pragma unroll
    for (int i = 0; i < 8; i++) {
        m_i[i] = -INFINITY;
        l_i[i] = 0.f;
#pragma unroll
        for (int j = 0; j < 8; j++) acc[i][j] = 0.f;
    }

    __syncthreads();

    for (int it = 0; it <= K_ANCH; it++) {
        int sel = (it < K_ANCH) ? anchors[(h * T_TILES + t) * K_ANCH + it] : t;
        if (sel > t) continue;   // fully-future tile: contributes nothing

        // Load K tile transposed: kv[d][c]. Rotated store -> 4-way (not 16-way)
        // bank conflicts.
#pragma unroll
        for (int l2 = 0; l2 < 16; l2++) {
            int chunk = tid + l2 * 256;
            int token = chunk >> 5;
            int d4    = chunk & 31;
            float4 a = *(const float4*)(kg + (sel * TILE + token) * HD + h * D_HEAD + (d4 << 2));
#pragma unroll
            for (int j = 0; j < 4; j++) {
                int u = (j + d4) & 3;
                float val = (u == 0) ? a.x : (u == 1) ? a.y : (u == 2) ? a.z : a.w;
                kv[(d4 * 4 + u) * PT + token] = val;
            }
        }
        __syncthreads();

        // S = Q * K^T  (8x8 micro-tile per thread, contraction over d)
        float s[8][8];
#pragma unroll
        for (int i = 0; i < 8; i++)
#pragma unroll
            for (int j = 0; j < 8; j++) s[i][j] = 0.f;

#pragma unroll 4
        for (int d = 0; d < 128; d++) {
            float af[8], bf[8];
#pragma unroll
            for (int i = 0; i < 8; i++) af[i] = qs[(ty * 8 + i) * PT + d];  // broadcast
            *(float4*)(bf)     = *(float4*)(kv + d * PT + tx * 8);
            *(float4*)(bf + 4) = *(float4*)(kv + d * PT + tx * 8 + 4);
#pragma unroll
            for (int i = 0; i < 8; i++)
#pragma unroll
                for (int j = 0; j < 8; j++)
                    s[i][j] += af[i] * bf[j];
        }

        // Mask + online softmax (row reductions via 16-lane xor shuffles)
        const bool diag = (sel == t);
#pragma unroll
        for (int i = 0; i < 8; i++) {
            int r = ty * 8 + i;
            float rm = -INFINITY;
#pragma unroll
            for (int j = 0; j < 8; j++) {
                float val = s[i][j] * sm_scale;
                if (diag && (tx * 8 + j) > r) val = -1.0e30f;  // causal (key > query)
                s[i][j] = val;
                rm = fmaxf(rm, val);
            }
#pragma unroll
            for (int off = 8; off > 0; off >>= 1)
                rm = fmaxf(rm, __shfl_xor_sync(0xffffffffu, rm, off));

            float mn = fmaxf(m_i[i], rm);
            float fs = __expf(m_i[i] - mn);   // first tile: exp(-inf)=0, acc is 0
            m_i[i] = mn;

            float rs = 0.f;
#pragma unroll
            for (int j = 0; j < 8; j++) {
                float p = __expf(s[i][j] - mn);
                s[i][j] = p;
                rs += p;
            }
#pragma unroll
            for (int off = 8; off > 0; off >>= 1)
                rs += __shfl_xor_sync(0xffffffffu, rs, off);

            l_i[i] = l_i[i] * fs + rs;
#pragma unroll
            for (int j = 0; j < 8; j++) acc[i][j] *= fs;

            // Store P row (natural, conflict-free float4)
            *(float4*)(ps + r * PT + tx * 8)     = make_float4(s[i][0], s[i][1], s[i][2], s[i][3]);
            *(float4*)(ps + r * PT + tx * 8 + 4) = make_float4(s[i][4], s[i][5], s[i][6], s[i][7]);
        }
        __syncthreads();

        // Load V tile natural [c][d] (overwrites K buffer)
#pragma unroll
        for (int l2 = 0; l2 < 16; l2++) {
            int chunk = tid + l2 * 256;
            int token = chunk >> 5;
            int d4    = (chunk & 31) << 2;
            *(float4*)(kv + token * PT + d4) =
                *(const float4*)(vg + (sel * TILE + token) * HD + h * D_HEAD + d4);
        }
        __syncthreads();

        // acc += P * V  (contraction over keys c)
#pragma unroll 4
        for (int c = 0; c < 128; c++) {
            float af[8], bf[8];
#pragma unroll
            for (int i = 0; i < 8; i++) af[i] = ps[(ty * 8 + i) * PT + c];  // broadcast
            *(float4*)(bf)     = *(float4*)(kv + c * PT + tx * 8);
            *(float4*)(bf + 4) = *(float4*)(kv + c * PT + tx * 8 + 4);
#pragma unroll
            for (int i = 0; i < 8; i++)
#pragma unroll
                for (int j = 0; j < 8; j++)
                    acc[i][j] += af[i] * bf[j];
        }
        __syncthreads();  // before next tile overwrites kv / ps
    }

    // Epilogue: out = acc / l  (l >= 1 guaranteed: local diagonal tile)
#pragma unroll
    for (int i = 0; i < 8; i++) {
        float inv = 1.0f / l_i[i];
        float* op = outg + (t * TILE + ty * 8 + i) * HD + h * D_HEAD + tx * 8;
        *(float4*)(op)     = make_float4(acc[i][0] * inv, acc[i][1] * inv,
                                         acc[i][2] * inv, acc[i][3] * inv);
        *(float4*)(op + 4) = make_float4(acc[i][4] * inv, acc[i][5] * inv,
                                         acc[i][6] * inv, acc[i][7] * inv);
    }
}

// ---------------------------------------------------------------------------
// Launch
// ---------------------------------------------------------------------------
extern "C" void kernel_launch(void* const* d_in, const int* in_sizes, int n_in,
                              void* d_out, int out_size)
{
    (void)in_sizes; (void)n_in; (void)out_size;
    const float* x   = (const float*)d_in[0];
    const float* wq  = (const float*)d_in[1];
    const float* wk  = (const float*)d_in[2];
    const float* wv  = (const float*)d_in[3];
    const float* wo  = (const float*)d_in[4];
    const float* ang = (const float*)d_in[5];
    const int* anchors = (const int*)d_in[6];
    float* out = (float*)d_out;

    float *qp, *kp, *vp, *ap;
    cudaGetSymbolAddress((void**)&qp, g_q);
    cudaGetSymbolAddress((void**)&kp, g_k);
    cudaGetSymbolAddress((void**)&vp, g_v);
    cudaGetSymbolAddress((void**)&ap, g_attn);

    dim3 gg(HD / BN, S_LEN / BM);   // (16, 32)

    // QKV projections
    sgemm_kernel<<<gg, 256>>>(x, wq, qp, S_LEN, HD, E_DIM);
    sgemm_kernel<<<gg, 256>>>(x, wk, kp, S_LEN, HD, E_DIM);
    sgemm_kernel<<<gg, 256>>>(x, wv, vp, S_LEN, HD, E_DIM);

    // RoPE on q, k
    rope_kernel<<<(S_LEN * H_NUM * 64 + 255) / 256, 256>>>(qp, kp, ang);

    // Block-sparse flash attention
    cudaFuncSetAttribute(attn_kernel, cudaFuncAttributeMaxDynamicSharedMemorySize, ATT_SMEM);
    attn_kernel<<<dim3(T_TILES, H_NUM), 256, ATT_SMEM>>>(qp, kp, vp, anchors, ap);

    // Output projection -> d_out
    sgemm_kernel<<<dim3(E_DIM / BN, S_LEN / BM), 256>>>(ap, wo, out, S_LEN, E_DIM, HD);
}

// round 3
// speedup vs baseline: 2.7794x; 2.7794x over previous
#include <cuda_runtime.h>
#include <cuda_bf16.h>
#include <cstdint>
#include <math.h>

#define S_LEN   4096
#define E_DIM   2048
#define H_NUM   16
#define D_HEAD  128
#define HD      2048
#define T_TILES 32
#define K_ANCH  8
#define TILE    128

// ---------------------------------------------------------------------------
// Device-global scratch
// ---------------------------------------------------------------------------
__device__ float g_q[S_LEN * HD];
__device__ float g_k[S_LEN * HD];
__device__ float g_v[S_LEN * HD];
__device__ float g_attn[S_LEN * HD];

__device__ __nv_bfloat16 g_xhi[S_LEN * E_DIM];
__device__ __nv_bfloat16 g_xlo[S_LEN * E_DIM];
__device__ __nv_bfloat16 g_ahi[S_LEN * HD];
__device__ __nv_bfloat16 g_alo[S_LEN * HD];

__device__ __nv_bfloat16 g_wqt_hi[E_DIM * HD];
__device__ __nv_bfloat16 g_wqt_lo[E_DIM * HD];
__device__ __nv_bfloat16 g_wkt_hi[E_DIM * HD];
__device__ __nv_bfloat16 g_wkt_lo[E_DIM * HD];
__device__ __nv_bfloat16 g_wvt_hi[E_DIM * HD];
__device__ __nv_bfloat16 g_wvt_lo[E_DIM * HD];
__device__ __nv_bfloat16 g_wot_hi[HD * E_DIM];
__device__ __nv_bfloat16 g_wot_lo[HD * E_DIM];

// ---------------------------------------------------------------------------
// PTX helpers (family-agnostic: mma.sync / ldmatrix / cp.async only)
// ---------------------------------------------------------------------------
__device__ __forceinline__ uint32_t smem_u32(const void* p) {
    uint32_t a;
    asm("{ .reg .u64 t; cvta.to.shared.u64 t, %1; cvt.u32.u64 %0, t; }" : "=r"(a) : "l"(p));
    return a;
}
__device__ __forceinline__ void cp16(uint32_t dst, const void* src) {
    asm volatile("cp.async.cg.shared.global [%0], [%1], 16;" :: "r"(dst), "l"(src));
}
__device__ __forceinline__ void cp_commit() {
    asm volatile("cp.async.commit_group;" ::: "memory");
}
template<int N>
__device__ __forceinline__ void cp_wait() {
    asm volatile("cp.async.wait_group %0;" :: "n"(N) : "memory");
}
__device__ __forceinline__ void ldm_x4(uint32_t* r, uint32_t addr) {
    asm volatile("ldmatrix.sync.aligned.m8n8.x4.shared.b16 {%0,%1,%2,%3}, [%4];"
        : "=r"(r[0]), "=r"(r[1]), "=r"(r[2]), "=r"(r[3]) : "r"(addr));
}
__device__ __forceinline__ uint32_t lds32(uint32_t addr) {
    uint32_t v;
    asm volatile("ld.shared.b32 %0, [%1];" : "=r"(v) : "r"(addr));
    return v;
}
__device__ __forceinline__ void mma_bf16(float* d, const uint32_t* a, const uint32_t* b) {
    asm volatile(
        "mma.sync.aligned.m16n8k16.row.col.f32.bf16.bf16.f32 "
        "{%0,%1,%2,%3}, {%4,%5,%6,%7}, {%8,%9}, {%0,%1,%2,%3};"
        : "+f"(d[0]), "+f"(d[1]), "+f"(d[2]), "+f"(d[3])
        : "r"(a[0]), "r"(a[1]), "r"(a[2]), "r"(a[3]), "r"(b[0]), "r"(b[1]));
}

// ---------------------------------------------------------------------------
// Split-bf16 tensor-core GEMM (mma.sync): C[M,N] = A[M,K] * Bt[N,K]^T
// CTA 128x128, 8 warps (2x4), warp tile 64x32, BK=32, double-buffered cp.async.
// C = Ahi*Bhi + Ahi*Blo + Alo*Bhi (fp32 accumulate).
// smem row pitch = 40 halves (80 B) -> conflict-free ldmatrix + lds.b32.
// ---------------------------------------------------------------------------
#define GPAD   40                      // halves per smem row
#define GT     (128 * GPAD * 2)        // bytes per 128x32 tile = 10240
#define GSTAGE (4 * GT)                // Ahi|Alo|Bhi|Blo = 40960
#define GSMEM  (2 * GSTAGE)            // 81920

__device__ __forceinline__ void g_load_stage(
    uint32_t sb, const __nv_bfloat16* Ahi, const __nv_bfloat16* Alo,
    const __nv_bfloat16* Bhi, const __nv_bfloat16* Blo, int ld, int tid)
{
    const __nv_bfloat16* srcs[4] = {Ahi, Alo, Bhi, Blo};
#pragma unroll
    for (int m = 0; m < 4; m++) {
        uint32_t d0 = sb + m * GT;
        const __nv_bfloat16* p = srcs[m];
#pragma unroll
        for (int i = tid; i < 512; i += 256) {
            int row = i >> 2, ch = i & 3;
            cp16(d0 + row * 80 + ch * 16, p + (size_t)row * ld + ch * 8);
        }
    }
}

__global__ __launch_bounds__(256, 1) void gemm_tc(
    const __nv_bfloat16* __restrict__ Ahi, const __nv_bfloat16* __restrict__ Alo,
    const __nv_bfloat16* __restrict__ Bhi, const __nv_bfloat16* __restrict__ Blo,
    float* __restrict__ C, int M, int N, int K)
{
    extern __shared__ char sm[];
    const uint32_t sb = smem_u32(sm);
    const int tid = threadIdx.x;
    const int wid = tid >> 5, lane = tid & 31;
    const int wm = wid >> 2, wn = wid & 3;           // warp grid 2 x 4
    const int g = lane >> 2, t = lane & 3;
    const int lrow = lane & 15, lk = (lane >> 4) * 8; // ldmatrix lane mapping
    const int mBase = blockIdx.y * 128;
    const int nBase = blockIdx.x * 128;
    const int nch = K / 32;

    float acc[4][4][4];
#pragma unroll
    for (int i = 0; i < 4; i++)
#pragma unroll
        for (int j = 0; j < 4; j++)
#pragma unroll
            for (int r = 0; r < 4; r++) acc[i][j][r] = 0.f;

    // prologue: stage 0
    g_load_stage(sb, Ahi + (size_t)mBase * K, Alo + (size_t)mBase * K,
                 Bhi + (size_t)nBase * K, Blo + (size_t)nBase * K, K, tid);
    cp_commit();

    for (int c = 0; c < nch; c++) {
        if (c + 1 < nch) {
            uint32_t nsb = sb + ((c + 1) & 1) * GSTAGE;
            const size_t ao = (size_t)mBase * K + (c + 1) * 32;
            const size_t bo = (size_t)nBase * K + (c + 1) * 32;
            g_load_stage(nsb, Ahi + ao, Alo + ao, Bhi + bo, Blo + bo, K, tid);
            cp_commit();
            cp_wait<1>();
        } else {
            cp_wait<0>();
        }
        __syncthreads();

        const uint32_t st = sb + (c & 1) * GSTAGE;
        const uint32_t A_hi = st, A_lo = st + GT, B_hi = st + 2 * GT, B_lo = st + 3 * GT;

#pragma unroll
        for (int ks = 0; ks < 2; ks++) {
            uint32_t ah[4][4], al[4][4], bh[4][2], bl[4][2];
#pragma unroll
            for (int mb = 0; mb < 4; mb++) {
                uint32_t off = (uint32_t)(wm * 64 + mb * 16 + lrow) * 80 + (ks * 16 + lk) * 2;
                ldm_x4(ah[mb], A_hi + off);
                ldm_x4(al[mb], A_lo + off);
            }
#pragma unroll
            for (int nb = 0; nb < 4; nb++) {
                uint32_t off = (uint32_t)(wn * 32 + nb * 8 + g) * 80 + (ks * 16 + t * 2) * 2;
                bh[nb][0] = lds32(B_hi + off);
                bh[nb][1] = lds32(B_hi + off + 16);
                bl[nb][0] = lds32(B_lo + off);
                bl[nb][1] = lds32(B_lo + off + 16);
            }
            // three passes: hi*hi, hi*lo, lo*hi (16 independent tiles between acc reuse)
#pragma unroll
            for (int mb = 0; mb < 4; mb++)
#pragma unroll
                for (int nb = 0; nb < 4; nb++) mma_bf16(acc[mb][nb], ah[mb], bh[nb]);
#pragma unroll
            for (int mb = 0; mb < 4; mb++)
#pragma unroll
                for (int nb = 0; nb < 4; nb++) mma_bf16(acc[mb][nb], ah[mb], bl[nb]);
#pragma unroll
            for (int mb = 0; mb < 4; mb++)
#pragma unroll
                for (int nb = 0; nb < 4; nb++) mma_bf16(acc[mb][nb], al[mb], bh[nb]);
        }
        __syncthreads();
    }

    // epilogue
#pragma unroll
    for (int mb = 0; mb < 4; mb++) {
#pragma unroll
        for (int nb = 0; nb < 4; nb++) {
            int row = mBase + wm * 64 + mb * 16 + g;
            int col = nBase + wn * 32 + nb * 8 + t * 2;
            *(float2*)(C + (size_t)row * N + col) = make_float2(acc[mb][nb][0], acc[mb][nb][1]);
            *(float2*)(C + (size_t)(row + 8) * N + col) = make_float2(acc[mb][nb][2], acc[mb][nb][3]);
        }
    }
}

// ---------------------------------------------------------------------------
// fp32 -> bf16 hi/lo split (elementwise)
// ---------------------------------------------------------------------------
__global__ __launch_bounds__(256) void conv_hilo(
    const float* __restrict__ A, __nv_bfloat16* __restrict__ hi,
    __nv_bfloat16* __restrict__ lo, int n4)
{
    int i = blockIdx.x * blockDim.x + threadIdx.x;
    if (i >= n4) return;
    float4 v = ((const float4*)A)[i];
    float f[4] = {v.x, v.y, v.z, v.w};
    uint32_t hw[2] = {0, 0}, lw[2] = {0, 0};
#pragma unroll
    for (int j = 0; j < 4; j++) {
        __nv_bfloat16 h = __float2bfloat16(f[j]);
        float rem = f[j] - __bfloat162float(h);
        __nv_bfloat16 l = __float2bfloat16(rem);
        hw[j >> 1] |= (uint32_t)__bfloat16_as_ushort(h) << ((j & 1) * 16);
        lw[j >> 1] |= (uint32_t)__bfloat16_as_ushort(l) << ((j & 1) * 16);
    }
    ((uint2*)hi)[i] = make_uint2(hw[0], hw[1]);
    ((uint2*)lo)[i] = make_uint2(lw[0], lw[1]);
}

// ---------------------------------------------------------------------------
// Weight transpose + split: W[K,N] fp32 -> Wt_hi/lo[N,K] bf16
// ---------------------------------------------------------------------------
__global__ __launch_bounds__(256) void convWT(
    const float* __restrict__ W, __nv_bfloat16* __restrict__ hi,
    __nv_bfloat16* __restrict__ lo, int K, int N)
{
    __shared__ float tb[32][33];
    const int n0 = blockIdx.x * 32, k0 = blockIdx.y * 32;
    const int tx = threadIdx.x, ty = threadIdx.y;  // 32 x 8
#pragma unroll
    for (int i = 0; i < 4; i++)
        tb[ty + i * 8][tx] = W[(size_t)(k0 + ty + i * 8) * N + n0 + tx];
    __syncthreads();
#pragma unroll
    for (int i = 0; i < 4; i++) {
        int n = n0 + ty + i * 8;
        float v = tb[tx][ty + i * 8];
        __nv_bfloat16 h = __float2bfloat16(v);
        float rem = v - __bfloat162float(h);
        hi[(size_t)n * K + k0 + tx] = h;
        lo[(size_t)n * K + k0 + tx] = __float2bfloat16(rem);
    }
}

// ---------------------------------------------------------------------------
// RoPE (half-split / rotate_half), in-place on q and k
// ---------------------------------------------------------------------------
__global__ __launch_bounds__(256) void rope_kernel(
    float* __restrict__ q, float* __restrict__ k, const float* __restrict__ ang)
{
    int idx = blockIdx.x * blockDim.x + threadIdx.x;
    if (idx >= S_LEN * H_NUM * 64) return;
    int p = idx & 63;
    int h = (idx >> 6) & 15;
    int s = idx >> 10;
    float a = ang[s * 64 + p];
    float c = cosf(a), sn = sinf(a);
    int base = s * HD + h * D_HEAD;

    float q0 = q[base + p], q1 = q[base + p + 64];
    q[base + p]      = q0 * c - q1 * sn;
    q[base + p + 64] = q1 * c + q0 * sn;

    float k0 = k[base + p], k1 = k[base + p + 64];
    k[base + p]      = k0 * c - k1 * sn;
    k[base + p + 64] = k1 * c + k0 * sn;
}

// ---------------------------------------------------------------------------
// Block-sparse flash attention (fp32 SIMT)
// ---------------------------------------------------------------------------
#define PT 132
#define ATT_SMEM (3 * 128 * PT * 4)

__global__ __launch_bounds__(256) void attn_kernel(
    const float* __restrict__ qg, const float* __restrict__ kg,
    const float* __restrict__ vg, const int* __restrict__ anchors,
    float* __restrict__ outg)
{
    extern __shared__ float smem[];
    float* qs = smem;
    float* kv = smem + 128 * PT;
    float* ps = smem + 2 * 128 * PT;

    const int t   = blockIdx.x;
    const int h   = blockIdx.y;
    const int tid = threadIdx.x;
    const int ty  = tid >> 4;
    const int tx  = tid & 15;
    const float sm_scale = 0.08838834764831845f;

#pragma unroll
    for (int it = 0; it < 16; it++) {
        int chunk = tid + it * 256;
        int token = chunk >> 5;
        int d4    = (chunk & 31) << 2;
        *(float4*)(qs + token * PT + d4) =
            *(const float4*)(qg + (t * TILE + token) * HD + h * D_HEAD + d4);
    }

    float m_i[8], l_i[8], acc[8][8];
#pragma unroll
    for (int i = 0; i < 8; i++) {
        m_i[i] = -INFINITY;
        l_i[i] = 0.f;
#pragma unroll
        for (int j = 0; j < 8; j++) acc[i][j] = 0.f;
    }
    __syncthreads();

    for (int it = 0; it <= K_ANCH; it++) {
        int sel = (it < K_ANCH) ? anchors[(h * T_TILES + t) * K_ANCH + it] : t;
        if (sel > t) continue;

#pragma unroll
        for (int l2 = 0; l2 < 16; l2++) {
            int chunk = tid + l2 * 256;
            int token = chunk >> 5;
            int d4    = chunk & 31;
            float4 a = *(const float4*)(kg + (sel * TILE + token) * HD + h * D_HEAD + (d4 << 2));
#pragma unroll
            for (int j = 0; j < 4; j++) {
                int u = (j + d4) & 3;
                float val = (u == 0) ? a.x : (u == 1) ? a.y : (u == 2) ? a.z : a.w;
                kv[(d4 * 4 + u) * PT + token] = val;
            }
        }
        __syncthreads();

        float s[8][8];
#pragma unroll
        for (int i = 0; i < 8; i++)
#pragma unroll
            for (int j = 0; j < 8; j++) s[i][j] = 0.f;

#pragma unroll 4
        for (int d = 0; d < 128; d++) {
            float af[8], bf[8];
#pragma unroll
            for (int i = 0; i < 8; i++) af[i] = qs[(ty * 8 + i) * PT + d];
            *(float4*)(bf)     = *(float4*)(kv + d * PT + tx * 8);
            *(float4*)(bf + 4) = *(float4*)(kv + d * PT + tx * 8 + 4);
#pragma unroll
            for (int i = 0; i < 8; i++)
#pragma unroll
                for (int j = 0; j < 8; j++)
                    s[i][j] += af[i] * bf[j];
        }

        const bool diag = (sel == t);
#pragma unroll
        for (int i = 0; i < 8; i++) {
            int r = ty * 8 + i;
            float rm = -INFINITY;
#pragma unroll
            for (int j = 0; j < 8; j++) {
                float val = s[i][j] * sm_scale;
                if (diag && (tx * 8 + j) > r) val = -1.0e30f;
                s[i][j] = val;
                rm = fmaxf(rm, val);
            }
#pragma unroll
            for (int off = 8; off > 0; off >>= 1)
                rm = fmaxf(rm, __shfl_xor_sync(0xffffffffu, rm, off));

            float mn = fmaxf(m_i[i], rm);
            float fs = __expf(m_i[i] - mn);
            m_i[i] = mn;

            float rs = 0.f;
#pragma unroll
            for (int j = 0; j < 8; j++) {
                float p = __expf(s[i][j] - mn);
                s[i][j] = p;
                rs += p;
            }
#pragma unroll
            for (int off = 8; off > 0; off >>= 1)
                rs += __shfl_xor_sync(0xffffffffu, rs, off);

            l_i[i] = l_i[i] * fs + rs;
#pragma unroll
            for (int j = 0; j < 8; j++) acc[i][j] *= fs;

            *(float4*)(ps + r * PT + tx * 8)     = make_float4(s[i][0], s[i][1], s[i][2], s[i][3]);
            *(float4*)(ps + r * PT + tx * 8 + 4) = make_float4(s[i][4], s[i][5], s[i][6], s[i][7]);
        }
        __syncthreads();

#pragma unroll
        for (int l2 = 0; l2 < 16; l2++) {
            int chunk = tid + l2 * 256;
            int token = chunk >> 5;
            int d4    = (chunk & 31) << 2;
            *(float4*)(kv + token * PT + d4) =
                *(const float4*)(vg + (sel * TILE + token) * HD + h * D_HEAD + d4);
        }
        __syncthreads();

#pragma unroll 4
        for (int c = 0; c < 128; c++) {
            float af[8], bf[8];
#pragma unroll
            for (int i = 0; i < 8; i++) af[i] = ps[(ty * 8 + i) * PT + c];
            *(float4*)(bf)     = *(float4*)(kv + c * PT + tx * 8);
            *(float4*)(bf + 4) = *(float4*)(kv + c * PT + tx * 8 + 4);
#pragma unroll
            for (int i = 0; i < 8; i++)
#pragma unroll
                for (int j = 0; j < 8; j++)
                    acc[i][j] += af[i] * bf[j];
        }
        __syncthreads();
    }

#pragma unroll
    for (int i = 0; i < 8; i++) {
        float inv = 1.0f / l_i[i];
        float* op = outg + (t * TILE + ty * 8 + i) * HD + h * D_HEAD + tx * 8;
        *(float4*)(op)     = make_float4(acc[i][0] * inv, acc[i][1] * inv,
                                         acc[i][2] * inv, acc[i][3] * inv);
        *(float4*)(op + 4) = make_float4(acc[i][4] * inv, acc[i][5] * inv,
                                         acc[i][6] * inv, acc[i][7] * inv);
    }
}

// ---------------------------------------------------------------------------
// Launch
// ---------------------------------------------------------------------------
extern "C" void kernel_launch(void* const* d_in, const int* in_sizes, int n_in,
                              void* d_out, int out_size)
{
    (void)in_sizes; (void)n_in; (void)out_size;
    const float* x   = (const float*)d_in[0];
    const float* wq  = (const float*)d_in[1];
    const float* wk  = (const float*)d_in[2];
    const float* wv  = (const float*)d_in[3];
    const float* wo  = (const float*)d_in[4];
    const float* ang = (const float*)d_in[5];
    const int* anchors = (const int*)d_in[6];
    float* out = (float*)d_out;

    float *qp, *kp, *vp, *ap;
    cudaGetSymbolAddress((void**)&qp, g_q);
    cudaGetSymbolAddress((void**)&kp, g_k);
    cudaGetSymbolAddress((void**)&vp, g_v);
    cudaGetSymbolAddress((void**)&ap, g_attn);

    __nv_bfloat16 *xhi, *xlo, *ahi, *alo;
    __nv_bfloat16 *wqh, *wql, *wkh, *wkl, *wvh, *wvl, *woh, *wol;
    cudaGetSymbolAddress((void**)&xhi, g_xhi);
    cudaGetSymbolAddress((void**)&xlo, g_xlo);
    cudaGetSymbolAddress((void**)&ahi, g_ahi);
    cudaGetSymbolAddress((void**)&alo, g_alo);
    cudaGetSymbolAddress((void**)&wqh, g_wqt_hi);
    cudaGetSymbolAddress((void**)&wql, g_wqt_lo);
    cudaGetSymbolAddress((void**)&wkh, g_wkt_hi);
    cudaGetSymbolAddress((void**)&wkl, g_wkt_lo);
    cudaGetSymbolAddress((void**)&wvh, g_wvt_hi);
    cudaGetSymbolAddress((void**)&wvl, g_wvt_lo);
    cudaGetSymbolAddress((void**)&woh, g_wot_hi);
    cudaGetSymbolAddress((void**)&wol, g_wot_lo);

    cudaFuncSetAttribute(gemm_tc, cudaFuncAttributeMaxDynamicSharedMemorySize, GSMEM);
    cudaFuncSetAttribute(attn_kernel, cudaFuncAttributeMaxDynamicSharedMemorySize, ATT_SMEM);

    // Split activations and weights
    const int n4x = S_LEN * E_DIM / 4;
    conv_hilo<<<(n4x + 255) / 256, 256>>>(x, xhi, xlo, n4x);
    dim3 wtg(HD / 32, E_DIM / 32);
    convWT<<<wtg, dim3(32, 8)>>>(wq, wqh, wql, E_DIM, HD);
    convWT<<<wtg, dim3(32, 8)>>>(wk, wkh, wkl, E_DIM, HD);
    convWT<<<wtg, dim3(32, 8)>>>(wv, wvh, wvl, E_DIM, HD);
    convWT<<<dim3(E_DIM / 32, HD / 32), dim3(32, 8)>>>(wo, woh, wol, HD, E_DIM);

    // QKV projections (mma.sync split-bf16)
    dim3 gg(HD / 128, S_LEN / 128);   // (16, 32)
    gemm_tc<<<gg, 256, GSMEM>>>(xhi, xlo, wqh, wql, qp, S_LEN, HD, E_DIM);
    gemm_tc<<<gg, 256, GSMEM>>>(xhi, xlo, wkh, wkl, kp, S_LEN, HD, E_DIM);
    gemm_tc<<<gg, 256, GSMEM>>>(xhi, xlo, wvh, wvl, vp, S_LEN, HD, E_DIM);

    // RoPE
    rope_kernel<<<(S_LEN * H_NUM * 64 + 255) / 256, 256>>>(qp, kp, ang);

    // Block-sparse flash attention
    attn_kernel<<<dim3(T_TILES, H_NUM), 256, ATT_SMEM>>>(qp, kp, vp, anchors, ap);

    // Output projection
    const int n4a = S_LEN * HD / 4;
    conv_hilo<<<(n4a + 255) / 256, 256>>>(ap, ahi, alo, n4a);
    gemm_tc<<<dim3(E_DIM / 128, S_LEN / 128), 256, GSMEM>>>(ahi, alo, woh, wol, out, S_LEN, E_DIM, HD);
}

// round 4
// speedup vs baseline: 3.2700x; 1.1765x over previous
#include <cuda_runtime.h>
#include <cuda_bf16.h>
#include <cstdint>
#include <math.h>

#define S_LEN   4096
#define E_DIM   2048
#define H_NUM   16
#define D_HEAD  128
#define HD      2048
#define NQKV    6144
#define T_TILES 32
#define K_ANCH  8
#define TILE    128

// ---------------------------------------------------------------------------
// Device-global scratch
// ---------------------------------------------------------------------------
__device__ float g_qkv[S_LEN * NQKV];       // fused Q|K|V, row stride 6144
__device__ float g_attn[S_LEN * HD];

__device__ __nv_bfloat16 g_xhi[S_LEN * E_DIM];
__device__ __nv_bfloat16 g_xlo[S_LEN * E_DIM];
__device__ __nv_bfloat16 g_ahi[S_LEN * HD];
__device__ __nv_bfloat16 g_alo[S_LEN * HD];

__device__ __nv_bfloat16 g_wt_hi[NQKV * E_DIM];   // [wq|wk|wv]^T, K-major
__device__ __nv_bfloat16 g_wt_lo[NQKV * E_DIM];
__device__ __nv_bfloat16 g_wot_hi[E_DIM * HD];
__device__ __nv_bfloat16 g_wot_lo[E_DIM * HD];

// ---------------------------------------------------------------------------
// PTX helpers (family-agnostic)
// ---------------------------------------------------------------------------
__device__ __forceinline__ uint32_t smem_u32(const void* p) {
    uint32_t a;
    asm("{ .reg .u64 t; cvta.to.shared.u64 t, %1; cvt.u32.u64 %0, t; }" : "=r"(a) : "l"(p));
    return a;
}
__device__ __forceinline__ void cp16(uint32_t dst, const void* src) {
    asm volatile("cp.async.cg.shared.global [%0], [%1], 16;" :: "r"(dst), "l"(src));
}
__device__ __forceinline__ void cp_commit() {
    asm volatile("cp.async.commit_group;" ::: "memory");
}
template<int N>
__device__ __forceinline__ void cp_wait() {
    asm volatile("cp.async.wait_group %0;" :: "n"(N) : "memory");
}
__device__ __forceinline__ void ldm_x4(uint32_t* r, uint32_t addr) {
    asm volatile("ldmatrix.sync.aligned.m8n8.x4.shared.b16 {%0,%1,%2,%3}, [%4];"
        : "=r"(r[0]), "=r"(r[1]), "=r"(r[2]), "=r"(r[3]) : "r"(addr));
}
__device__ __forceinline__ void mma_bf16(float* d, const uint32_t* a, const uint32_t* b) {
    asm volatile(
        "mma.sync.aligned.m16n8k16.row.col.f32.bf16.bf16.f32 "
        "{%0,%1,%2,%3}, {%4,%5,%6,%7}, {%8,%9}, {%0,%1,%2,%3};"
        : "+f"(d[0]), "+f"(d[1]), "+f"(d[2]), "+f"(d[3])
        : "r"(a[0]), "r"(a[1]), "r"(a[2]), "r"(a[3]), "r"(b[0]), "r"(b[1]));
}

// ---------------------------------------------------------------------------
// Split-bf16 tensor-core GEMM: C[M,N] = A[M,K] * Bt[N,K]^T
// CTA 128x128, 4 warps (2x2), warp tile 64x64, BK=32, 2-stage cp.async,
// 2 CTAs/SM. C = Ahi*Bhi + Alo*Bhi + Ahi*Blo (fp32 accumulate).
// smem: per stage 4 sections (Ahi|Alo|Bhi|Blo) of 128 rows x 80B pitch.
// ---------------------------------------------------------------------------
#define GSEC   10240                   // 128 rows * 80 B
#define GSTAGE (4 * GSEC)              // 40960
#define GSMEM  (2 * GSTAGE)            // 81920

__device__ __forceinline__ void g_load_stage(
    uint32_t sb, const __nv_bfloat16* pAh, const __nv_bfloat16* pAl,
    const __nv_bfloat16* pBh, const __nv_bfloat16* pBl, int K, int tid)
{
    const __nv_bfloat16* secp[4] = {pAh, pAl, pBh, pBl};
#pragma unroll
    for (int idx = tid; idx < 2048; idx += 128) {
        int row = idx >> 2, ch = idx & 3;
        int sec = row >> 7, r = row & 127;
        cp16(sb + sec * GSEC + r * 80 + ch * 16, secp[sec] + (size_t)r * K + ch * 8);
    }
}

__global__ __launch_bounds__(128, 2) void gemm_tc(
    const __nv_bfloat16* __restrict__ Ahi, const __nv_bfloat16* __restrict__ Alo,
    const __nv_bfloat16* __restrict__ Bhi, const __nv_bfloat16* __restrict__ Blo,
    float* __restrict__ C, int M, int N, int K)
{
    extern __shared__ char sm[];
    const uint32_t sb = smem_u32(sm);
    const int tid = threadIdx.x;
    const int wid = tid >> 5, lane = tid & 31;
    const int wm = wid >> 1, wn = wid & 1;            // warp grid 2 x 2
    const int g = lane >> 2, t = lane & 3;
    const int lrow = lane & 15, lk2 = (lane >> 4) * 16;     // A ldmatrix mapping
    const int brow = (lane & 7) + ((lane >> 4) & 1) * 8;    // B ldmatrix mapping
    const int bk2 = ((lane >> 3) & 1) * 16;
    const int mBase = blockIdx.y * 128;
    const int nBase = blockIdx.x * 128;
    const int nch = K / 32;

    float acc[4][8][4];
#pragma unroll
    for (int i = 0; i < 4; i++)
#pragma unroll
        for (int j = 0; j < 8; j++)
#pragma unroll
            for (int r = 0; r < 4; r++) acc[i][j][r] = 0.f;

    const __nv_bfloat16* pAh = Ahi + (size_t)mBase * K;
    const __nv_bfloat16* pAl = Alo + (size_t)mBase * K;
    const __nv_bfloat16* pBh = Bhi + (size_t)nBase * K;
    const __nv_bfloat16* pBl = Blo + (size_t)nBase * K;

    g_load_stage(sb, pAh, pAl, pBh, pBl, K, tid);
    cp_commit();

    for (int c = 0; c < nch; c++) {
        if (c + 1 < nch) {
            g_load_stage(sb + ((c + 1) & 1) * GSTAGE,
                         pAh + (c + 1) * 32, pAl + (c + 1) * 32,
                         pBh + (c + 1) * 32, pBl + (c + 1) * 32, K, tid);
            cp_commit();
            cp_wait<1>();
        } else {
            cp_wait<0>();
        }
        __syncthreads();

        const uint32_t st = sb + (c & 1) * GSTAGE;

#pragma unroll
        for (int ks = 0; ks < 2; ks++) {
            uint32_t ah[4][4], al[4][4], bb[16];
            // A fragments (hi then lo)
#pragma unroll
            for (int mb = 0; mb < 4; mb++) {
                uint32_t ao = (uint32_t)(wm * 64 + mb * 16 + lrow) * 80 + ks * 32 + lk2;
                ldm_x4(ah[mb], st + ao);
                ldm_x4(al[mb], st + GSEC + ao);
            }
            // B hi fragments (8 nb blocks via 4 ldmatrix.x4)
#pragma unroll
            for (int p = 0; p < 4; p++) {
                uint32_t bo = (uint32_t)(wn * 64 + p * 16 + brow) * 80 + ks * 32 + bk2;
                ldm_x4(bb + p * 4, st + 2 * GSEC + bo);
            }
            // pass 1: Ahi * Bhi ; pass 2: Alo * Bhi
#pragma unroll
            for (int mb = 0; mb < 4; mb++)
#pragma unroll
                for (int nb = 0; nb < 8; nb++) mma_bf16(acc[mb][nb], ah[mb], bb + nb * 2);
#pragma unroll
            for (int mb = 0; mb < 4; mb++)
#pragma unroll
                for (int nb = 0; nb < 8; nb++) mma_bf16(acc[mb][nb], al[mb], bb + nb * 2);
            // reload B lo over bb, pass 3: Ahi * Blo
#pragma unroll
            for (int p = 0; p < 4; p++) {
                uint32_t bo = (uint32_t)(wn * 64 + p * 16 + brow) * 80 + ks * 32 + bk2;
                ldm_x4(bb + p * 4, st + 3 * GSEC + bo);
            }
#pragma unroll
            for (int mb = 0; mb < 4; mb++)
#pragma unroll
                for (int nb = 0; nb < 8; nb++) mma_bf16(acc[mb][nb], ah[mb], bb + nb * 2);
        }
        __syncthreads();
    }

    // epilogue
#pragma unroll
    for (int mb = 0; mb < 4; mb++) {
#pragma unroll
        for (int nb = 0; nb < 8; nb++) {
            int row = mBase + wm * 64 + mb * 16 + g;
            int col = nBase + wn * 64 + nb * 8 + t * 2;
            *(float2*)(C + (size_t)row * N + col) = make_float2(acc[mb][nb][0], acc[mb][nb][1]);
            *(float2*)(C + (size_t)(row + 8) * N + col) = make_float2(acc[mb][nb][2], acc[mb][nb][3]);
        }
    }
}

// ---------------------------------------------------------------------------
// fp32 -> bf16 hi/lo split (elementwise)
// ---------------------------------------------------------------------------
__global__ __launch_bounds__(256) void conv_hilo(
    const float* __restrict__ A, __nv_bfloat16* __restrict__ hi,
    __nv_bfloat16* __restrict__ lo, int n4)
{
    int i = blockIdx.x * blockDim.x + threadIdx.x;
    if (i >= n4) return;
    float4 v = ((const float4*)A)[i];
    float f[4] = {v.x, v.y, v.z, v.w};
    uint32_t hw[2] = {0, 0}, lw[2] = {0, 0};
#pragma unroll
    for (int j = 0; j < 4; j++) {
        __nv_bfloat16 h = __float2bfloat16(f[j]);
        float rem = f[j] - __bfloat162float(h);
        __nv_bfloat16 l = __float2bfloat16(rem);
        hw[j >> 1] |= (uint32_t)__bfloat16_as_ushort(h) << ((j & 1) * 16);
        lw[j >> 1] |= (uint32_t)__bfloat16_as_ushort(l) << ((j & 1) * 16);
    }
    ((uint2*)hi)[i] = make_uint2(hw[0], hw[1]);
    ((uint2*)lo)[i] = make_uint2(lw[0], lw[1]);
}

// ---------------------------------------------------------------------------
// Weight transpose + split: W[K,N] fp32 -> Wt_hi/lo[outOff+N, K] bf16
// ---------------------------------------------------------------------------
__global__ __launch_bounds__(256) void convWT(
    const float* __restrict__ W, __nv_bfloat16* __restrict__ hi,
    __nv_bfloat16* __restrict__ lo, int K, int N, int outOff)
{
    __shared__ float tb[32][33];
    const int n0 = blockIdx.x * 32, k0 = blockIdx.y * 32;
    const int tx = threadIdx.x, ty = threadIdx.y;  // 32 x 8
#pragma unroll
    for (int i = 0; i < 4; i++)
        tb[ty + i * 8][tx] = W[(size_t)(k0 + ty + i * 8) * N + n0 + tx];
    __syncthreads();
#pragma unroll
    for (int i = 0; i < 4; i++) {
        int n = outOff + n0 + ty + i * 8;
        float v = tb[tx][ty + i * 8];
        __nv_bfloat16 h = __float2bfloat16(v);
        float rem = v - __bfloat162float(h);
        hi[(size_t)n * K + k0 + tx] = h;
        lo[(size_t)n * K + k0 + tx] = __float2bfloat16(rem);
    }
}

// ---------------------------------------------------------------------------
// RoPE in-place on the q and k sections of the fused qkv buffer
// ---------------------------------------------------------------------------
__global__ __launch_bounds__(256) void rope_kernel(
    float* __restrict__ qkv, const float* __restrict__ ang)
{
    int idx = blockIdx.x * blockDim.x + threadIdx.x;
    if (idx >= S_LEN * H_NUM * 64) return;
    int p = idx & 63;
    int h = (idx >> 6) & 15;
    int s = idx >> 10;
    float a = ang[s * 64 + p];
    float c = cosf(a), sn = sinf(a);
    size_t base = (size_t)s * NQKV + h * D_HEAD;

    float q0 = qkv[base + p], q1 = qkv[base + p + 64];
    qkv[base + p]      = q0 * c - q1 * sn;
    qkv[base + p + 64] = q1 * c + q0 * sn;

    size_t kb = base + HD;
    float k0 = qkv[kb + p], k1 = qkv[kb + p + 64];
    qkv[kb + p]      = k0 * c - k1 * sn;
    qkv[kb + p + 64] = k1 * c + k0 * sn;
}

// ---------------------------------------------------------------------------
// Block-sparse flash attention (fp32 SIMT) reading fused qkv (stride 6144)
// ---------------------------------------------------------------------------
#define PT 132
#define ATT_SMEM (3 * 128 * PT * 4)

__global__ __launch_bounds__(256) void attn_kernel(
    const float* __restrict__ qkv, const int* __restrict__ anchors,
    float* __restrict__ outg)
{
    extern __shared__ float smem[];
    float* qs = smem;
    float* kv = smem + 128 * PT;
    float* ps = smem + 2 * 128 * PT;

    const int t   = blockIdx.x;
    const int h   = blockIdx.y;
    const int tid = threadIdx.x;
    const int ty  = tid >> 4;
    const int tx  = tid & 15;
    const float sm_scale = 0.08838834764831845f;

    const float* qg = qkv + h * D_HEAD;
    const float* kg = qkv + HD + h * D_HEAD;
    const float* vg = qkv + 2 * HD + h * D_HEAD;

#pragma unroll
    for (int it = 0; it < 16; it++) {
        int chunk = tid + it * 256;
        int token = chunk >> 5;
        int d4    = (chunk & 31) << 2;
        *(float4*)(qs + token * PT + d4) =
            *(const float4*)(qg + (size_t)(t * TILE + token) * NQKV + d4);
    }

    float m_i[8], l_i[8], acc[8][8];
#pragma unroll
    for (int i = 0; i < 8; i++) {
        m_i[i] = -INFINITY;
        l_i[i] = 0.f;
#pragma unroll
        for (int j = 0; j < 8; j++) acc[i][j] = 0.f;
    }
    __syncthreads();

    for (int it = 0; it <= K_ANCH; it++) {
        int sel = (it < K_ANCH) ? anchors[(h * T_TILES + t) * K_ANCH + it] : t;
        if (sel > t) continue;

#pragma unroll
        for (int l2 = 0; l2 < 16; l2++) {
            int chunk = tid + l2 * 256;
            int token = chunk >> 5;
            int d4    = chunk & 31;
            float4 a = *(const float4*)(kg + (size_t)(sel * TILE + token) * NQKV + (d4 << 2));
#pragma unroll
            for (int j = 0; j < 4; j++) {
                int u = (j + d4) & 3;
                float val = (u == 0) ? a.x : (u == 1) ? a.y : (u == 2) ? a.z : a.w;
                kv[(d4 * 4 + u) * PT + token] = val;
            }
        }
        __syncthreads();

        float s[8][8];
#pragma unroll
        for (int i = 0; i < 8; i++)
#pragma unroll
            for (int j = 0; j < 8; j++) s[i][j] = 0.f;

#pragma unroll 4
        for (int d = 0; d < 128; d++) {
            float af[8], bf[8];
#pragma unroll
            for (int i = 0; i < 8; i++) af[i] = qs[(ty * 8 + i) * PT + d];
            *(float4*)(bf)     = *(float4*)(kv + d * PT + tx * 8);
            *(float4*)(bf + 4) = *(float4*)(kv + d * PT + tx * 8 + 4);
#pragma unroll
            for (int i = 0; i < 8; i++)
#pragma unroll
                for (int j = 0; j < 8; j++)
                    s[i][j] += af[i] * bf[j];
        }

        const bool diag = (sel == t);
#pragma unroll
        for (int i = 0; i < 8; i++) {
            int r = ty * 8 + i;
            float rm = -INFINITY;
#pragma unroll
            for (int j = 0; j < 8; j++) {
                float val = s[i][j] * sm_scale;
                if (diag && (tx * 8 + j) > r) val = -1.0e30f;
                s[i][j] = val;
                rm = fmaxf(rm, val);
            }
#pragma unroll
            for (int off = 8; off > 0; off >>= 1)
                rm = fmaxf(rm, __shfl_xor_sync(0xffffffffu, rm, off));

            float mn = fmaxf(m_i[i], rm);
            float fs = __expf(m_i[i] - mn);
            m_i[i] = mn;

            float rs = 0.f;
#pragma unroll
            for (int j = 0; j < 8; j++) {
                float p = __expf(s[i][j] - mn);
                s[i][j] = p;
                rs += p;
            }
#pragma unroll
            for (int off = 8; off > 0; off >>= 1)
                rs += __shfl_xor_sync(0xffffffffu, rs, off);

            l_i[i] = l_i[i] * fs + rs;
#pragma unroll
            for (int j = 0; j < 8; j++) acc[i][j] *= fs;

            *(float4*)(ps + r * PT + tx * 8)     = make_float4(s[i][0], s[i][1], s[i][2], s[i][3]);
            *(float4*)(ps + r * PT + tx * 8 + 4) = make_float4(s[i][4], s[i][5], s[i][6], s[i][7]);
        }
        __syncthreads();

#pragma unroll
        for (int l2 = 0; l2 < 16; l2++) {
            int chunk = tid + l2 * 256;
            int token = chunk >> 5;
            int d4    = (chunk & 31) << 2;
            *(float4*)(kv + token * PT + d4) =
                *(const float4*)(vg + (size_t)(sel * TILE + token) * NQKV + d4);
        }
        __syncthreads();

#pragma unroll 4
        for (int c = 0; c < 128; c++) {
            float af[8], bf[8];
#pragma unroll
            for (int i = 0; i < 8; i++) af[i] = ps[(ty * 8 + i) * PT + c];
            *(float4*)(bf)     = *(float4*)(kv + c * PT + tx * 8);
            *(float4*)(bf + 4) = *(float4*)(kv + c * PT + tx * 8 + 4);
#pragma unroll
            for (int i = 0; i < 8; i++)
#pragma unroll
                for (int j = 0; j < 8; j++)
                    acc[i][j] += af[i] * bf[j];
        }
        __syncthreads();
    }

#pragma unroll
    for (int i = 0; i < 8; i++) {
        float inv = 1.0f / l_i[i];
        float* op = outg + (size_t)(t * TILE + ty * 8 + i) * HD + h * D_HEAD + tx * 8;
        *(float4*)(op)     = make_float4(acc[i][0] * inv, acc[i][1] * inv,
                                         acc[i][2] * inv, acc[i][3] * inv);
        *(float4*)(op + 4) = make_float4(acc[i][4] * inv, acc[i][5] * inv,
                                         acc[i][6] * inv, acc[i][7] * inv);
    }
}

// ---------------------------------------------------------------------------
// Launch
// ---------------------------------------------------------------------------
extern "C" void kernel_launch(void* const* d_in, const int* in_sizes, int n_in,
                              void* d_out, int out_size)
{
    (void)in_sizes; (void)n_in; (void)out_size;
    const float* x   = (const float*)d_in[0];
    const float* wq  = (const float*)d_in[1];
    const float* wk  = (const float*)d_in[2];
    const float* wv  = (const float*)d_in[3];
    const float* wo  = (const float*)d_in[4];
    const float* ang = (const float*)d_in[5];
    const int* anchors = (const int*)d_in[6];
    float* out = (float*)d_out;

    float *qkv, *ap;
    cudaGetSymbolAddress((void**)&qkv, g_qkv);
    cudaGetSymbolAddress((void**)&ap, g_attn);

    __nv_bfloat16 *xhi, *xlo, *ahi, *alo, *wth, *wtl, *woh, *wol;
    cudaGetSymbolAddress((void**)&xhi, g_xhi);
    cudaGetSymbolAddress((void**)&xlo, g_xlo);
    cudaGetSymbolAddress((void**)&ahi, g_ahi);
    cudaGetSymbolAddress((void**)&alo, g_alo);
    cudaGetSymbolAddress((void**)&wth, g_wt_hi);
    cudaGetSymbolAddress((void**)&wtl, g_wt_lo);
    cudaGetSymbolAddress((void**)&woh, g_wot_hi);
    cudaGetSymbolAddress((void**)&wol, g_wot_lo);

    cudaFuncSetAttribute(gemm_tc, cudaFuncAttributeMaxDynamicSharedMemorySize, GSMEM);
    cudaFuncSetAttribute(attn_kernel, cudaFuncAttributeMaxDynamicSharedMemorySize, ATT_SMEM);

    // Split activations + transpose/split weights (wq|wk|wv fused)
    const int n4x = S_LEN * E_DIM / 4;
    conv_hilo<<<(n4x + 255) / 256, 256>>>(x, xhi, xlo, n4x);
    dim3 wtg(HD / 32, E_DIM / 32);
    convWT<<<wtg, dim3(32, 8)>>>(wq, wth, wtl, E_DIM, HD, 0);
    convWT<<<wtg, dim3(32, 8)>>>(wk, wth, wtl, E_DIM, HD, HD);
    convWT<<<wtg, dim3(32, 8)>>>(wv, wth, wtl, E_DIM, HD, 2 * HD);
    convWT<<<dim3(E_DIM / 32, HD / 32), dim3(32, 8)>>>(wo, woh, wol, HD, E_DIM, 0);

    // Fused QKV projection: [4096, 6144]
    gemm_tc<<<dim3(NQKV / 128, S_LEN / 128), 128, GSMEM>>>(
        xhi, xlo, wth, wtl, qkv, S_LEN, NQKV, E_DIM);

    // RoPE on q,k sections
    rope_kernel<<<(S_LEN * H_NUM * 64 + 255) / 256, 256>>>(qkv, ang);

    // Block-sparse flash attention
    attn_kernel<<<dim3(T_TILES, H_NUM), 256, ATT_SMEM>>>(qkv, anchors, ap);

    // Output projection
    const int n4a = S_LEN * HD / 4;
    conv_hilo<<<(n4a + 255) / 256, 256>>>(ap, ahi, alo, n4a);
    gemm_tc<<<dim3(E_DIM / 128, S_LEN / 128), 128, GSMEM>>>(
        ahi, alo, woh, wol, out, S_LEN, E_DIM, HD);
}

// round 5
// speedup vs baseline: 4.4387x; 1.3574x over previous
#include <cuda_runtime.h>
#include <cuda_bf16.h>
#include <cstdint>
#include <math.h>

#define S_LEN   4096
#define E_DIM   2048
#define H_NUM   16
#define D_HEAD  128
#define HD      2048
#define NQKV    6144
#define T_TILES 32
#define K_ANCH  8
#define TILE    128

// ---------------------------------------------------------------------------
// Device-global scratch
// ---------------------------------------------------------------------------
__device__ float g_qkv[S_LEN * NQKV];       // fused Q|K|V fp32 (gemm output)
__device__ float g_attn[S_LEN * HD];

__device__ __nv_bfloat16 g_qkvh[S_LEN * NQKV];   // post-RoPE bf16 hi
__device__ __nv_bfloat16 g_qkvl[S_LEN * NQKV];   // post-RoPE bf16 lo

__device__ __nv_bfloat16 g_xhi[S_LEN * E_DIM];
__device__ __nv_bfloat16 g_xlo[S_LEN * E_DIM];
__device__ __nv_bfloat16 g_ahi[S_LEN * HD];
__device__ __nv_bfloat16 g_alo[S_LEN * HD];

__device__ __nv_bfloat16 g_wt_hi[NQKV * E_DIM];   // [wq|wk|wv]^T, K-major
__device__ __nv_bfloat16 g_wt_lo[NQKV * E_DIM];
__device__ __nv_bfloat16 g_wot_hi[E_DIM * HD];
__device__ __nv_bfloat16 g_wot_lo[E_DIM * HD];

// ---------------------------------------------------------------------------
// PTX helpers (family-agnostic)
// ---------------------------------------------------------------------------
__device__ __forceinline__ uint32_t smem_u32(const void* p) {
    uint32_t a;
    asm("{ .reg .u64 t; cvta.to.shared.u64 t, %1; cvt.u32.u64 %0, t; }" : "=r"(a) : "l"(p));
    return a;
}
__device__ __forceinline__ void cp16(uint32_t dst, const void* src) {
    asm volatile("cp.async.cg.shared.global [%0], [%1], 16;" :: "r"(dst), "l"(src));
}
__device__ __forceinline__ void cp_commit() {
    asm volatile("cp.async.commit_group;" ::: "memory");
}
template<int N>
__device__ __forceinline__ void cp_wait() {
    asm volatile("cp.async.wait_group %0;" :: "n"(N) : "memory");
}
__device__ __forceinline__ void ldm_x4(uint32_t* r, uint32_t addr) {
    asm volatile("ldmatrix.sync.aligned.m8n8.x4.shared.b16 {%0,%1,%2,%3}, [%4];"
        : "=r"(r[0]), "=r"(r[1]), "=r"(r[2]), "=r"(r[3]) : "r"(addr));
}
__device__ __forceinline__ void ldm_x4_t(uint32_t* r, uint32_t addr) {
    asm volatile("ldmatrix.sync.aligned.m8n8.x4.trans.shared.b16 {%0,%1,%2,%3}, [%4];"
        : "=r"(r[0]), "=r"(r[1]), "=r"(r[2]), "=r"(r[3]) : "r"(addr));
}
__device__ __forceinline__ void mma_bf16(float* d, const uint32_t* a, const uint32_t* b) {
    asm volatile(
        "mma.sync.aligned.m16n8k16.row.col.f32.bf16.bf16.f32 "
        "{%0,%1,%2,%3}, {%4,%5,%6,%7}, {%8,%9}, {%0,%1,%2,%3};"
        : "+f"(d[0]), "+f"(d[1]), "+f"(d[2]), "+f"(d[3])
        : "r"(a[0]), "r"(a[1]), "r"(a[2]), "r"(a[3]), "r"(b[0]), "r"(b[1]));
}
// pack two fp32 into bf16x2: low half = lo, high half = hi
__device__ __forceinline__ uint32_t pack_bf16(float lo, float hi) {
    uint32_t d;
    asm("cvt.rn.bf16x2.f32 %0, %1, %2;" : "=r"(d) : "f"(hi), "f"(lo));
    return d;
}

// ---------------------------------------------------------------------------
// Split-bf16 tensor-core GEMM (unchanged from R4): C[M,N] = A[M,K]*Bt[N,K]^T
// ---------------------------------------------------------------------------
#define GSEC   10240
#define GSTAGE (4 * GSEC)
#define GSMEM  (2 * GSTAGE)

__device__ __forceinline__ void g_load_stage(
    uint32_t sb, const __nv_bfloat16* pAh, const __nv_bfloat16* pAl,
    const __nv_bfloat16* pBh, const __nv_bfloat16* pBl, int K, int tid)
{
    const __nv_bfloat16* secp[4] = {pAh, pAl, pBh, pBl};
#pragma unroll
    for (int idx = tid; idx < 2048; idx += 128) {
        int row = idx >> 2, ch = idx & 3;
        int sec = row >> 7, r = row & 127;
        cp16(sb + sec * GSEC + r * 80 + ch * 16, secp[sec] + (size_t)r * K + ch * 8);
    }
}

__global__ __launch_bounds__(128, 2) void gemm_tc(
    const __nv_bfloat16* __restrict__ Ahi, const __nv_bfloat16* __restrict__ Alo,
    const __nv_bfloat16* __restrict__ Bhi, const __nv_bfloat16* __restrict__ Blo,
    float* __restrict__ C, int M, int N, int K)
{
    extern __shared__ char sm[];
    const uint32_t sb = smem_u32(sm);
    const int tid = threadIdx.x;
    const int wid = tid >> 5, lane = tid & 31;
    const int wm = wid >> 1, wn = wid & 1;
    const int g = lane >> 2, t = lane & 3;
    const int lrow = lane & 15, lk2 = (lane >> 4) * 16;
    const int brow = (lane & 7) + ((lane >> 4) & 1) * 8;
    const int bk2 = ((lane >> 3) & 1) * 16;
    const int mBase = blockIdx.y * 128;
    const int nBase = blockIdx.x * 128;
    const int nch = K / 32;

    float acc[4][8][4];
#pragma unroll
    for (int i = 0; i < 4; i++)
#pragma unroll
        for (int j = 0; j < 8; j++)
#pragma unroll
            for (int r = 0; r < 4; r++) acc[i][j][r] = 0.f;

    const __nv_bfloat16* pAh = Ahi + (size_t)mBase * K;
    const __nv_bfloat16* pAl = Alo + (size_t)mBase * K;
    const __nv_bfloat16* pBh = Bhi + (size_t)nBase * K;
    const __nv_bfloat16* pBl = Blo + (size_t)nBase * K;

    g_load_stage(sb, pAh, pAl, pBh, pBl, K, tid);
    cp_commit();

    for (int c = 0; c < nch; c++) {
        if (c + 1 < nch) {
            g_load_stage(sb + ((c + 1) & 1) * GSTAGE,
                         pAh + (c + 1) * 32, pAl + (c + 1) * 32,
                         pBh + (c + 1) * 32, pBl + (c + 1) * 32, K, tid);
            cp_commit();
            cp_wait<1>();
        } else {
            cp_wait<0>();
        }
        __syncthreads();

        const uint32_t st = sb + (c & 1) * GSTAGE;

#pragma unroll
        for (int ks = 0; ks < 2; ks++) {
            uint32_t ah[4][4], al[4][4], bb[16];
#pragma unroll
            for (int mb = 0; mb < 4; mb++) {
                uint32_t ao = (uint32_t)(wm * 64 + mb * 16 + lrow) * 80 + ks * 32 + lk2;
                ldm_x4(ah[mb], st + ao);
                ldm_x4(al[mb], st + GSEC + ao);
            }
#pragma unroll
            for (int p = 0; p < 4; p++) {
                uint32_t bo = (uint32_t)(wn * 64 + p * 16 + brow) * 80 + ks * 32 + bk2;
                ldm_x4(bb + p * 4, st + 2 * GSEC + bo);
            }
#pragma unroll
            for (int mb = 0; mb < 4; mb++)
#pragma unroll
                for (int nb = 0; nb < 8; nb++) mma_bf16(acc[mb][nb], ah[mb], bb + nb * 2);
#pragma unroll
            for (int mb = 0; mb < 4; mb++)
#pragma unroll
                for (int nb = 0; nb < 8; nb++) mma_bf16(acc[mb][nb], al[mb], bb + nb * 2);
#pragma unroll
            for (int p = 0; p < 4; p++) {
                uint32_t bo = (uint32_t)(wn * 64 + p * 16 + brow) * 80 + ks * 32 + bk2;
                ldm_x4(bb + p * 4, st + 3 * GSEC + bo);
            }
#pragma unroll
            for (int mb = 0; mb < 4; mb++)
#pragma unroll
                for (int nb = 0; nb < 8; nb++) mma_bf16(acc[mb][nb], ah[mb], bb + nb * 2);
        }
        __syncthreads();
    }

#pragma unroll
    for (int mb = 0; mb < 4; mb++) {
#pragma unroll
        for (int nb = 0; nb < 8; nb++) {
            int row = mBase + wm * 64 + mb * 16 + g;
            int col = nBase + wn * 64 + nb * 8 + t * 2;
            *(float2*)(C + (size_t)row * N + col) = make_float2(acc[mb][nb][0], acc[mb][nb][1]);
            *(float2*)(C + (size_t)(row + 8) * N + col) = make_float2(acc[mb][nb][2], acc[mb][nb][3]);
        }
    }
}

// ---------------------------------------------------------------------------
// fp32 -> bf16 hi/lo split (elementwise)
// ---------------------------------------------------------------------------
__global__ __launch_bounds__(256) void conv_hilo(
    const float* __restrict__ A, __nv_bfloat16* __restrict__ hi,
    __nv_bfloat16* __restrict__ lo, int n4)
{
    int i = blockIdx.x * blockDim.x + threadIdx.x;
    if (i >= n4) return;
    float4 v = ((const float4*)A)[i];
    float f[4] = {v.x, v.y, v.z, v.w};
    uint32_t hw[2] = {0, 0}, lw[2] = {0, 0};
#pragma unroll
    for (int j = 0; j < 4; j++) {
        __nv_bfloat16 h = __float2bfloat16(f[j]);
        float rem = f[j] - __bfloat162float(h);
        __nv_bfloat16 l = __float2bfloat16(rem);
        hw[j >> 1] |= (uint32_t)__bfloat16_as_ushort(h) << ((j & 1) * 16);
        lw[j >> 1] |= (uint32_t)__bfloat16_as_ushort(l) << ((j & 1) * 16);
    }
    ((uint2*)hi)[i] = make_uint2(hw[0], hw[1]);
    ((uint2*)lo)[i] = make_uint2(lw[0], lw[1]);
}

// ---------------------------------------------------------------------------
// Weight transpose + split
// ---------------------------------------------------------------------------
__global__ __launch_bounds__(256) void convWT(
    const float* __restrict__ W, __nv_bfloat16* __restrict__ hi,
    __nv_bfloat16* __restrict__ lo, int K, int N, int outOff)
{
    __shared__ float tb[32][33];
    const int n0 = blockIdx.x * 32, k0 = blockIdx.y * 32;
    const int tx = threadIdx.x, ty = threadIdx.y;
#pragma unroll
    for (int i = 0; i < 4; i++)
        tb[ty + i * 8][tx] = W[(size_t)(k0 + ty + i * 8) * N + n0 + tx];
    __syncthreads();
#pragma unroll
    for (int i = 0; i < 4; i++) {
        int n = outOff + n0 + ty + i * 8;
        float v = tb[tx][ty + i * 8];
        __nv_bfloat16 h = __float2bfloat16(v);
        float rem = v - __bfloat162float(h);
        hi[(size_t)n * K + k0 + tx] = h;
        lo[(size_t)n * K + k0 + tx] = __float2bfloat16(rem);
    }
}

// ---------------------------------------------------------------------------
// RoPE + hi/lo bf16 conversion of the fused qkv buffer.
// grid (12, S_LEN), 256 threads. blk 0..47 of 128 cols; q,k = blk<32 roped.
// ---------------------------------------------------------------------------
__global__ __launch_bounds__(256) void rope_conv(
    const float* __restrict__ qkv, const float* __restrict__ ang,
    __nv_bfloat16* __restrict__ oh, __nv_bfloat16* __restrict__ ol)
{
    int ir = blockIdx.x * 256 + threadIdx.x;    // 0..3071
    int s = blockIdx.y;
    int blk = ir >> 6, p = ir & 63;
    size_t base = (size_t)s * NQKV + blk * 128;
    float f0 = qkv[base + p], f1 = qkv[base + p + 64];
    if (blk < 32) {
        float a = ang[s * 64 + p];
        float c = cosf(a), sn = sinf(a);
        float n0 = f0 * c - f1 * sn;
        float n1 = f1 * c + f0 * sn;
        f0 = n0; f1 = n1;
    }
    __nv_bfloat16 h0 = __float2bfloat16(f0);
    __nv_bfloat16 h1 = __float2bfloat16(f1);
    oh[base + p]      = h0;
    oh[base + p + 64] = h1;
    ol[base + p]      = __float2bfloat16(f0 - __bfloat162float(h0));
    ol[base + p + 64] = __float2bfloat16(f1 - __bfloat162float(h1));
}

// ---------------------------------------------------------------------------
// Tensor-core block-sparse flash attention (split-bf16, 3-term).
// CTA = (q-tile t, head h), 8 warps, warp = 16 query rows.
// smem: Q hi|lo persistent, K hi|lo (overwritten by V hi|lo per tile).
// pitch 136 halves (272 B) -> conflict-free ldmatrix.
// ---------------------------------------------------------------------------
#define APITCH 136
#define AQH 0
#define AQL (128 * APITCH)
#define AKH (2 * 128 * APITCH)
#define AKL (3 * 128 * APITCH)
#define ATT_SMEM (4 * 128 * APITCH * 2)   // 139264 bytes

__global__ __launch_bounds__(256, 1) void attn_tc(
    const __nv_bfloat16* __restrict__ qkvh, const __nv_bfloat16* __restrict__ qkvl,
    const int* __restrict__ anchors, float* __restrict__ outg)
{
    extern __shared__ __nv_bfloat16 asmem[];
    const uint32_t sb = smem_u32(asmem);
    const int t = blockIdx.x, h = blockIdx.y;
    const int tid = threadIdx.x, wid = tid >> 5, lane = tid & 31;
    const int g = lane >> 2, tq = lane & 3;
    const int lrow = lane & 15, lk2 = (lane >> 4) * 16;       // A (Q / row-major) map
    const int brow = (lane & 7) + ((lane >> 4) & 1) * 8;      // B (K / K-major) map
    const int bk2 = ((lane >> 3) & 1) * 16;
    const int vm = lane >> 3, vr = lane & 7;                  // B trans (V) map
    const float sm_scale = 0.08838834764831845f;

    // Load Q hi/lo (persistent)
    {
        const __nv_bfloat16* qh = qkvh + (size_t)(t * TILE) * NQKV + h * D_HEAD;
        const __nv_bfloat16* ql = qkvl + (size_t)(t * TILE) * NQKV + h * D_HEAD;
        for (int i = tid; i < 2048; i += 256) {
            int row = i >> 4, ch = i & 15;
            cp16(sb + (AQH + row * APITCH) * 2 + ch * 16, qh + (size_t)row * NQKV + ch * 8);
            cp16(sb + (AQL + row * APITCH) * 2 + ch * 16, ql + (size_t)row * NQKV + ch * 8);
        }
        cp_commit();
    }

    float o[16][4];
#pragma unroll
    for (int i = 0; i < 16; i++)
#pragma unroll
        for (int j = 0; j < 4; j++) o[i][j] = 0.f;
    float m0 = -INFINITY, m1 = -INFINITY, l0 = 0.f, l1 = 0.f;

    cp_wait<0>();
    __syncthreads();

    for (int it = 0; it <= K_ANCH; it++) {
        int sel = (it < K_ANCH) ? anchors[(h * T_TILES + t) * K_ANCH + it] : t;
        if (sel > t) continue;

        // ---- Load K hi/lo ----
        {
            const __nv_bfloat16* kh = qkvh + (size_t)(sel * TILE) * NQKV + HD + h * D_HEAD;
            const __nv_bfloat16* kl = qkvl + (size_t)(sel * TILE) * NQKV + HD + h * D_HEAD;
            for (int i = tid; i < 2048; i += 256) {
                int row = i >> 4, ch = i & 15;
                cp16(sb + (AKH + row * APITCH) * 2 + ch * 16, kh + (size_t)row * NQKV + ch * 8);
                cp16(sb + (AKL + row * APITCH) * 2 + ch * 16, kl + (size_t)row * NQKV + ch * 8);
            }
            cp_commit(); cp_wait<0>();
        }
        __syncthreads();

        // ---- S = Q K^T (3-term split-bf16) ----
        float S[16][4];
#pragma unroll
        for (int i = 0; i < 16; i++)
#pragma unroll
            for (int j = 0; j < 4; j++) S[i][j] = 0.f;

#pragma unroll
        for (int ks = 0; ks < 8; ks++) {
            uint32_t ah[4], al[4];
            uint32_t ao = (uint32_t)((wid * 16 + lrow) * APITCH) * 2 + ks * 32 + lk2;
            ldm_x4(ah, sb + AQH * 2 + ao);
            ldm_x4(al, sb + AQL * 2 + ao);
#pragma unroll
            for (int p = 0; p < 8; p++) {
                uint32_t bb[4];
                uint32_t bo = (uint32_t)((p * 16 + brow) * APITCH) * 2 + ks * 32 + bk2;
                ldm_x4(bb, sb + AKH * 2 + bo);
                mma_bf16(S[2 * p],     ah, bb);
                mma_bf16(S[2 * p + 1], ah, bb + 2);
                mma_bf16(S[2 * p],     al, bb);
                mma_bf16(S[2 * p + 1], al, bb + 2);
                ldm_x4(bb, sb + AKL * 2 + bo);
                mma_bf16(S[2 * p],     ah, bb);
                mma_bf16(S[2 * p + 1], ah, bb + 2);
            }
        }

        // ---- online softmax on fragments ----
        const bool diag = (sel == t);
        const int qr0 = wid * 16 + g;          // local query row (row1 = qr0+8)
        float mx0 = -INFINITY, mx1 = -INFINITY;
#pragma unroll
        for (int nb = 0; nb < 16; nb++) {
            int c0 = nb * 8 + tq * 2, c1 = c0 + 1;
            float v0 = S[nb][0] * sm_scale, v1 = S[nb][1] * sm_scale;
            float v2 = S[nb][2] * sm_scale, v3 = S[nb][3] * sm_scale;
            if (diag) {
                if (c0 > qr0) v0 = -INFINITY;
                if (c1 > qr0) v1 = -INFINITY;
                if (c0 > qr0 + 8) v2 = -INFINITY;
                if (c1 > qr0 + 8) v3 = -INFINITY;
            }
            S[nb][0] = v0; S[nb][1] = v1; S[nb][2] = v2; S[nb][3] = v3;
            mx0 = fmaxf(mx0, fmaxf(v0, v1));
            mx1 = fmaxf(mx1, fmaxf(v2, v3));
        }
        mx0 = fmaxf(mx0, __shfl_xor_sync(0xffffffffu, mx0, 1));
        mx0 = fmaxf(mx0, __shfl_xor_sync(0xffffffffu, mx0, 2));
        mx1 = fmaxf(mx1, __shfl_xor_sync(0xffffffffu, mx1, 1));
        mx1 = fmaxf(mx1, __shfl_xor_sync(0xffffffffu, mx1, 2));

        float mn0 = fmaxf(m0, mx0), mn1 = fmaxf(m1, mx1);
        float fs0 = __expf(m0 - mn0), fs1 = __expf(m1 - mn1);
        m0 = mn0; m1 = mn1;

        float rs0 = 0.f, rs1 = 0.f;
#pragma unroll
        for (int nb = 0; nb < 16; nb++) {
            float p0 = __expf(S[nb][0] - mn0);
            float p1 = __expf(S[nb][1] - mn0);
            float p2 = __expf(S[nb][2] - mn1);
            float p3 = __expf(S[nb][3] - mn1);
            S[nb][0] = p0; S[nb][1] = p1; S[nb][2] = p2; S[nb][3] = p3;
            rs0 += p0 + p1; rs1 += p2 + p3;
        }
        rs0 += __shfl_xor_sync(0xffffffffu, rs0, 1);
        rs0 += __shfl_xor_sync(0xffffffffu, rs0, 2);
        rs1 += __shfl_xor_sync(0xffffffffu, rs1, 1);
        rs1 += __shfl_xor_sync(0xffffffffu, rs1, 2);
        l0 = l0 * fs0 + rs0;
        l1 = l1 * fs1 + rs1;
#pragma unroll
        for (int nb = 0; nb < 16; nb++) {
            o[nb][0] *= fs0; o[nb][1] *= fs0;
            o[nb][2] *= fs1; o[nb][3] *= fs1;
        }

        // ---- Load V hi/lo (overwrites K smem) ----
        __syncthreads();
        {
            const __nv_bfloat16* vh = qkvh + (size_t)(sel * TILE) * NQKV + 2 * HD + h * D_HEAD;
            const __nv_bfloat16* vl = qkvl + (size_t)(sel * TILE) * NQKV + 2 * HD + h * D_HEAD;
            for (int i = tid; i < 2048; i += 256) {
                int row = i >> 4, ch = i & 15;
                cp16(sb + (AKH + row * APITCH) * 2 + ch * 16, vh + (size_t)row * NQKV + ch * 8);
                cp16(sb + (AKL + row * APITCH) * 2 + ch * 16, vl + (size_t)row * NQKV + ch * 8);
            }
            cp_commit(); cp_wait<0>();
        }
        __syncthreads();

        // ---- O += P V (3-term: Phi*Vhi + Plo*Vhi + Phi*Vlo) ----
#pragma unroll
        for (int j = 0; j < 8; j++) {
            // pack P fragments (A layout) from S regs
            uint32_t ph[4], pl[4];
            float p00 = S[2 * j][0],     p01 = S[2 * j][1];
            float p10 = S[2 * j][2],     p11 = S[2 * j][3];
            float q00 = S[2 * j + 1][0], q01 = S[2 * j + 1][1];
            float q10 = S[2 * j + 1][2], q11 = S[2 * j + 1][3];
            ph[0] = pack_bf16(p00, p01);
            ph[1] = pack_bf16(p10, p11);
            ph[2] = pack_bf16(q00, q01);
            ph[3] = pack_bf16(q10, q11);
            pl[0] = pack_bf16(p00 - __uint_as_float(ph[0] << 16),
                              p01 - __uint_as_float(ph[0] & 0xffff0000u));
            pl[1] = pack_bf16(p10 - __uint_as_float(ph[1] << 16),
                              p11 - __uint_as_float(ph[1] & 0xffff0000u));
            pl[2] = pack_bf16(q00 - __uint_as_float(ph[2] << 16),
                              q01 - __uint_as_float(ph[2] & 0xffff0000u));
            pl[3] = pack_bf16(q10 - __uint_as_float(ph[3] << 16),
                              q11 - __uint_as_float(ph[3] & 0xffff0000u));

            uint32_t vrow = (uint32_t)(j * 16 + (vm & 1) * 8 + vr) * APITCH * 2;
#pragma unroll
            for (int p = 0; p < 8; p++) {
                uint32_t vb[4];
                uint32_t vo = vrow + (uint32_t)(p * 32 + (vm >> 1) * 16);
                ldm_x4_t(vb, sb + AKH * 2 + vo);
                mma_bf16(o[2 * p],     ph, vb);
                mma_bf16(o[2 * p + 1], ph, vb + 2);
                mma_bf16(o[2 * p],     pl, vb);
                mma_bf16(o[2 * p + 1], pl, vb + 2);
                ldm_x4_t(vb, sb + AKL * 2 + vo);
                mma_bf16(o[2 * p],     ph, vb);
                mma_bf16(o[2 * p + 1], ph, vb + 2);
            }
        }
        __syncthreads();   // before next tile overwrites K/V smem
    }

    // ---- epilogue ----
    float inv0 = 1.0f / l0, inv1 = 1.0f / l1;
    int row0 = t * TILE + wid * 16 + g;
#pragma unroll
    for (int nb = 0; nb < 16; nb++) {
        float* p0 = outg + (size_t)row0 * HD + h * D_HEAD + nb * 8 + tq * 2;
        *(float2*)p0 = make_float2(o[nb][0] * inv0, o[nb][1] * inv0);
        *(float2*)(p0 + 8 * HD) = make_float2(o[nb][2] * inv1, o[nb][3] * inv1);
    }
}

// ---------------------------------------------------------------------------
// Launch
// ---------------------------------------------------------------------------
extern "C" void kernel_launch(void* const* d_in, const int* in_sizes, int n_in,
                              void* d_out, int out_size)
{
    (void)in_sizes; (void)n_in; (void)out_size;
    const float* x   = (const float*)d_in[0];
    const float* wq  = (const float*)d_in[1];
    const float* wk  = (const float*)d_in[2];
    const float* wv  = (const float*)d_in[3];
    const float* wo  = (const float*)d_in[4];
    const float* ang = (const float*)d_in[5];
    const int* anchors = (const int*)d_in[6];
    float* out = (float*)d_out;

    float *qkv, *ap;
    cudaGetSymbolAddress((void**)&qkv, g_qkv);
    cudaGetSymbolAddress((void**)&ap, g_attn);

    __nv_bfloat16 *qkvh, *qkvl, *xhi, *xlo, *ahi, *alo, *wth, *wtl, *woh, *wol;
    cudaGetSymbolAddress((void**)&qkvh, g_qkvh);
    cudaGetSymbolAddress((void**)&qkvl, g_qkvl);
    cudaGetSymbolAddress((void**)&xhi, g_xhi);
    cudaGetSymbolAddress((void**)&xlo, g_xlo);
    cudaGetSymbolAddress((void**)&ahi, g_ahi);
    cudaGetSymbolAddress((void**)&alo, g_alo);
    cudaGetSymbolAddress((void**)&wth, g_wt_hi);
    cudaGetSymbolAddress((void**)&wtl, g_wt_lo);
    cudaGetSymbolAddress((void**)&woh, g_wot_hi);
    cudaGetSymbolAddress((void**)&wol, g_wot_lo);

    cudaFuncSetAttribute(gemm_tc, cudaFuncAttributeMaxDynamicSharedMemorySize, GSMEM);
    cudaFuncSetAttribute(attn_tc, cudaFuncAttributeMaxDynamicSharedMemorySize, ATT_SMEM);

    // Split activations + transpose/split weights
    const int n4x = S_LEN * E_DIM / 4;
    conv_hilo<<<(n4x + 255) / 256, 256>>>(x, xhi, xlo, n4x);
    dim3 wtg(HD / 32, E_DIM / 32);
    convWT<<<wtg, dim3(32, 8)>>>(wq, wth, wtl, E_DIM, HD, 0);
    convWT<<<wtg, dim3(32, 8)>>>(wk, wth, wtl, E_DIM, HD, HD);
    convWT<<<wtg, dim3(32, 8)>>>(wv, wth, wtl, E_DIM, HD, 2 * HD);
    convWT<<<dim3(E_DIM / 32, HD / 32), dim3(32, 8)>>>(wo, woh, wol, HD, E_DIM, 0);

    // Fused QKV projection
    gemm_tc<<<dim3(NQKV / 128, S_LEN / 128), 128, GSMEM>>>(
        xhi, xlo, wth, wtl, qkv, S_LEN, NQKV, E_DIM);

    // RoPE + bf16 hi/lo conversion
    rope_conv<<<dim3(12, S_LEN), 256>>>(qkv, ang, qkvh, qkvl);

    // Tensor-core block-sparse flash attention
    attn_tc<<<dim3(T_TILES, H_NUM), 256, ATT_SMEM>>>(qkvh, qkvl, anchors, ap);

    // Output projection
    const int n4a = S_LEN * HD / 4;
    conv_hilo<<<(n4a + 255) / 256, 256>>>(ap, ahi, alo, n4a);
    gemm_tc<<<dim3(E_DIM / 128, S_LEN / 128), 128, GSMEM>>>(
        ahi, alo, woh, wol, out, S_LEN, E_DIM, HD);
}

// round 6
// speedup vs baseline: 4.9400x; 1.1129x over previous
#include <cuda_runtime.h>
#include <cuda_bf16.h>
#include <cstdint>
#include <math.h>

#define S_LEN   4096
#define E_DIM   2048
#define H_NUM   16
#define D_HEAD  128
#define HD      2048
#define NQKV    6144
#define T_TILES 32
#define K_ANCH  8
#define TILE    128

// ---------------------------------------------------------------------------
// Device-global scratch
// ---------------------------------------------------------------------------
__device__ __nv_bfloat16 g_qkvh[S_LEN * NQKV];   // post-RoPE bf16 hi
__device__ __nv_bfloat16 g_qkvl[S_LEN * NQKV];   // post-RoPE bf16 lo

__device__ __nv_bfloat16 g_xhi[S_LEN * E_DIM];
__device__ __nv_bfloat16 g_xlo[S_LEN * E_DIM];
__device__ __nv_bfloat16 g_ahi[S_LEN * HD];
__device__ __nv_bfloat16 g_alo[S_LEN * HD];

__device__ __nv_bfloat16 g_wt_hi[NQKV * E_DIM];   // [wq|wk|wv]^T, K-major
__device__ __nv_bfloat16 g_wt_lo[NQKV * E_DIM];
__device__ __nv_bfloat16 g_wot_hi[E_DIM * HD];
__device__ __nv_bfloat16 g_wot_lo[E_DIM * HD];

// ---------------------------------------------------------------------------
// PTX helpers (family-agnostic)
// ---------------------------------------------------------------------------
__device__ __forceinline__ uint32_t smem_u32(const void* p) {
    uint32_t a;
    asm("{ .reg .u64 t; cvta.to.shared.u64 t, %1; cvt.u32.u64 %0, t; }" : "=r"(a) : "l"(p));
    return a;
}
__device__ __forceinline__ void cp16(uint32_t dst, const void* src) {
    asm volatile("cp.async.cg.shared.global [%0], [%1], 16;" :: "r"(dst), "l"(src));
}
__device__ __forceinline__ void cp_commit() {
    asm volatile("cp.async.commit_group;" ::: "memory");
}
template<int N>
__device__ __forceinline__ void cp_wait() {
    asm volatile("cp.async.wait_group %0;" :: "n"(N) : "memory");
}
__device__ __forceinline__ void ldm_x4(uint32_t* r, uint32_t addr) {
    asm volatile("ldmatrix.sync.aligned.m8n8.x4.shared.b16 {%0,%1,%2,%3}, [%4];"
        : "=r"(r[0]), "=r"(r[1]), "=r"(r[2]), "=r"(r[3]) : "r"(addr));
}
__device__ __forceinline__ void ldm_x4_t(uint32_t* r, uint32_t addr) {
    asm volatile("ldmatrix.sync.aligned.m8n8.x4.trans.shared.b16 {%0,%1,%2,%3}, [%4];"
        : "=r"(r[0]), "=r"(r[1]), "=r"(r[2]), "=r"(r[3]) : "r"(addr));
}
__device__ __forceinline__ void mma_bf16(float* d, const uint32_t* a, const uint32_t* b) {
    asm volatile(
        "mma.sync.aligned.m16n8k16.row.col.f32.bf16.bf16.f32 "
        "{%0,%1,%2,%3}, {%4,%5,%6,%7}, {%8,%9}, {%0,%1,%2,%3};"
        : "+f"(d[0]), "+f"(d[1]), "+f"(d[2]), "+f"(d[3])
        : "r"(a[0]), "r"(a[1]), "r"(a[2]), "r"(a[3]), "r"(b[0]), "r"(b[1]));
}
// pack two fp32 -> bf16x2 (low half = first arg)
__device__ __forceinline__ uint32_t pack_bf16(float lo, float hi) {
    uint32_t d;
    asm("cvt.rn.bf16x2.f32 %0, %1, %2;" : "=r"(d) : "f"(hi), "f"(lo));
    return d;
}
// split float[8] -> hi uint4 + lo uint4 (bf16x2 packed)
__device__ __forceinline__ void split8(const float* v, uint4& H, uint4& L) {
    uint32_t hw[4], lw[4];
#pragma unroll
    for (int j = 0; j < 4; j++) {
        float a = v[2 * j], b = v[2 * j + 1];
        hw[j] = pack_bf16(a, b);
        lw[j] = pack_bf16(a - __uint_as_float(hw[j] << 16),
                          b - __uint_as_float(hw[j] & 0xffff0000u));
    }
    H = make_uint4(hw[0], hw[1], hw[2], hw[3]);
    L = make_uint4(lw[0], lw[1], lw[2], lw[3]);
}

// ---------------------------------------------------------------------------
// Split-bf16 tensor-core GEMM: C = A * Bt^T.
// mode 0: write C fp32. mode 1 (QKV): epilogue applies RoPE (tiles with
// blockIdx.x < 32, i.e. Q|K sections) + hi/lo bf16 split, writes qh/ql.
// ---------------------------------------------------------------------------
#define GSEC   10240
#define GSTAGE (4 * GSEC)
#define GSMEM  (2 * GSTAGE)

__device__ __forceinline__ void g_load_stage(
    uint32_t sb, const __nv_bfloat16* pAh, const __nv_bfloat16* pAl,
    const __nv_bfloat16* pBh, const __nv_bfloat16* pBl, int K, int tid)
{
    const __nv_bfloat16* secp[4] = {pAh, pAl, pBh, pBl};
#pragma unroll
    for (int idx = tid; idx < 2048; idx += 128) {
        int row = idx >> 2, ch = idx & 3;
        int sec = row >> 7, r = row & 127;
        cp16(sb + sec * GSEC + r * 80 + ch * 16, secp[sec] + (size_t)r * K + ch * 8);
    }
}

__global__ __launch_bounds__(128, 2) void gemm_tc(
    const __nv_bfloat16* __restrict__ Ahi, const __nv_bfloat16* __restrict__ Alo,
    const __nv_bfloat16* __restrict__ Bhi, const __nv_bfloat16* __restrict__ Blo,
    float* __restrict__ C,
    __nv_bfloat16* __restrict__ qh, __nv_bfloat16* __restrict__ ql,
    const float* __restrict__ ang,
    int M, int N, int K, int mode)
{
    extern __shared__ char sm[];
    const uint32_t sb = smem_u32(sm);
    const int tid = threadIdx.x;
    const int wid = tid >> 5, lane = tid & 31;
    const int wm = wid >> 1, wn = wid & 1;
    const int g = lane >> 2, t = lane & 3;
    const int lrow = lane & 15, lk2 = (lane >> 4) * 16;
    const int brow = (lane & 7) + ((lane >> 4) & 1) * 8;
    const int bk2 = ((lane >> 3) & 1) * 16;
    const int mBase = blockIdx.y * 128;
    const int nBase = blockIdx.x * 128;
    const int nch = K / 32;

    float acc[4][8][4];
#pragma unroll
    for (int i = 0; i < 4; i++)
#pragma unroll
        for (int j = 0; j < 8; j++)
#pragma unroll
            for (int r = 0; r < 4; r++) acc[i][j][r] = 0.f;

    const __nv_bfloat16* pAh = Ahi + (size_t)mBase * K;
    const __nv_bfloat16* pAl = Alo + (size_t)mBase * K;
    const __nv_bfloat16* pBh = Bhi + (size_t)nBase * K;
    const __nv_bfloat16* pBl = Blo + (size_t)nBase * K;

    g_load_stage(sb, pAh, pAl, pBh, pBl, K, tid);
    cp_commit();

    for (int c = 0; c < nch; c++) {
        if (c + 1 < nch) {
            g_load_stage(sb + ((c + 1) & 1) * GSTAGE,
                         pAh + (c + 1) * 32, pAl + (c + 1) * 32,
                         pBh + (c + 1) * 32, pBl + (c + 1) * 32, K, tid);
            cp_commit();
            cp_wait<1>();
        } else {
            cp_wait<0>();
        }
        __syncthreads();

        const uint32_t st = sb + (c & 1) * GSTAGE;

#pragma unroll
        for (int ks = 0; ks < 2; ks++) {
            uint32_t ah[4][4], al[4][4], bb[16];
#pragma unroll
            for (int mb = 0; mb < 4; mb++) {
                uint32_t ao = (uint32_t)(wm * 64 + mb * 16 + lrow) * 80 + ks * 32 + lk2;
                ldm_x4(ah[mb], st + ao);
                ldm_x4(al[mb], st + GSEC + ao);
            }
#pragma unroll
            for (int p = 0; p < 4; p++) {
                uint32_t bo = (uint32_t)(wn * 64 + p * 16 + brow) * 80 + ks * 32 + bk2;
                ldm_x4(bb + p * 4, st + 2 * GSEC + bo);
            }
#pragma unroll
            for (int mb = 0; mb < 4; mb++)
#pragma unroll
                for (int nb = 0; nb < 8; nb++) mma_bf16(acc[mb][nb], ah[mb], bb + nb * 2);
#pragma unroll
            for (int mb = 0; mb < 4; mb++)
#pragma unroll
                for (int nb = 0; nb < 8; nb++) mma_bf16(acc[mb][nb], al[mb], bb + nb * 2);
#pragma unroll
            for (int p = 0; p < 4; p++) {
                uint32_t bo = (uint32_t)(wn * 64 + p * 16 + brow) * 80 + ks * 32 + bk2;
                ldm_x4(bb + p * 4, st + 3 * GSEC + bo);
            }
#pragma unroll
            for (int mb = 0; mb < 4; mb++)
#pragma unroll
                for (int nb = 0; nb < 8; nb++) mma_bf16(acc[mb][nb], ah[mb], bb + nb * 2);
        }
        __syncthreads();
    }

    if (mode == 0) {
#pragma unroll
        for (int mb = 0; mb < 4; mb++) {
#pragma unroll
            for (int nb = 0; nb < 8; nb++) {
                int row = mBase + wm * 64 + mb * 16 + g;
                int col = nBase + wn * 64 + nb * 8 + t * 2;
                *(float2*)(C + (size_t)row * N + col) = make_float2(acc[mb][nb][0], acc[mb][nb][1]);
                *(float2*)(C + (size_t)(row + 8) * N + col) = make_float2(acc[mb][nb][2], acc[mb][nb][3]);
            }
        }
        return;
    }

    // ---- mode 1: RoPE (Q|K tiles) + hi/lo bf16 split epilogue ----
    float* cs = (float*)sm;   // [128][132] fp32, reuses stage smem (post-sync)
#pragma unroll
    for (int mb = 0; mb < 4; mb++) {
#pragma unroll
        for (int nb = 0; nb < 8; nb++) {
            int r0 = wm * 64 + mb * 16 + g;
            int cl = wn * 64 + nb * 8 + t * 2;
            *(float2*)(cs + r0 * 132 + cl) = make_float2(acc[mb][nb][0], acc[mb][nb][1]);
            *(float2*)(cs + (r0 + 8) * 132 + cl) = make_float2(acc[mb][nb][2], acc[mb][nb][3]);
        }
    }
    __syncthreads();

    const bool doRope = (blockIdx.x < 32);   // Q and K sections
    const int cch = tid & 7;                 // column chunk 0..7 (cols cch*8..+7)
    const int rg  = tid >> 3;                // row group 0..15
#pragma unroll 1
    for (int itr = 0; itr < 8; itr++) {
        int r = rg + itr * 16;
        int srow = mBase + r;
        float f0[8], f1[8], o0[8], o1[8];
        *(float4*)(f0)     = *(float4*)(cs + r * 132 + cch * 8);
        *(float4*)(f0 + 4) = *(float4*)(cs + r * 132 + cch * 8 + 4);
        *(float4*)(f1)     = *(float4*)(cs + r * 132 + cch * 8 + 64);
        *(float4*)(f1 + 4) = *(float4*)(cs + r * 132 + cch * 8 + 68);
        if (doRope) {
            float av[8];
            *(float4*)(av)     = *(const float4*)(ang + (size_t)srow * 64 + cch * 8);
            *(float4*)(av + 4) = *(const float4*)(ang + (size_t)srow * 64 + cch * 8 + 4);
#pragma unroll
            for (int j = 0; j < 8; j++) {
                float cc = __cosf(av[j]), ss = __sinf(av[j]);
                o0[j] = f0[j] * cc - f1[j] * ss;
                o1[j] = f1[j] * cc + f0[j] * ss;
            }
        } else {
#pragma unroll
            for (int j = 0; j < 8; j++) { o0[j] = f0[j]; o1[j] = f1[j]; }
        }
        uint4 H, L;
        size_t base = (size_t)srow * NQKV + nBase + cch * 8;
        split8(o0, H, L);
        *(uint4*)(qh + base) = H;
        *(uint4*)(ql + base) = L;
        split8(o1, H, L);
        *(uint4*)(qh + base + 64) = H;
        *(uint4*)(ql + base + 64) = L;
    }
}

// ---------------------------------------------------------------------------
// fp32 -> bf16 hi/lo split (elementwise, for x)
// ---------------------------------------------------------------------------
__global__ __launch_bounds__(256) void conv_hilo(
    const float* __restrict__ A, __nv_bfloat16* __restrict__ hi,
    __nv_bfloat16* __restrict__ lo, int n4)
{
    int i = blockIdx.x * blockDim.x + threadIdx.x;
    if (i >= n4) return;
    float4 v = ((const float4*)A)[i];
    float f[4] = {v.x, v.y, v.z, v.w};
    uint32_t hw[2] = {0, 0}, lw[2] = {0, 0};
#pragma unroll
    for (int j = 0; j < 4; j++) {
        __nv_bfloat16 h = __float2bfloat16(f[j]);
        float rem = f[j] - __bfloat162float(h);
        __nv_bfloat16 l = __float2bfloat16(rem);
        hw[j >> 1] |= (uint32_t)__bfloat16_as_ushort(h) << ((j & 1) * 16);
        lw[j >> 1] |= (uint32_t)__bfloat16_as_ushort(l) << ((j & 1) * 16);
    }
    ((uint2*)hi)[i] = make_uint2(hw[0], hw[1]);
    ((uint2*)lo)[i] = make_uint2(lw[0], lw[1]);
}

// ---------------------------------------------------------------------------
// Weight transpose + split. convWT3 handles wq|wk|wv via blockIdx.z.
// ---------------------------------------------------------------------------
__device__ __forceinline__ void wt_body(
    const float* W, __nv_bfloat16* hi, __nv_bfloat16* lo, int K, int N, int outOff)
{
    __shared__ float tb[32][33];
    const int n0 = blockIdx.x * 32, k0 = blockIdx.y * 32;
    const int tx = threadIdx.x, ty = threadIdx.y;
#pragma unroll
    for (int i = 0; i < 4; i++)
        tb[ty + i * 8][tx] = W[(size_t)(k0 + ty + i * 8) * N + n0 + tx];
    __syncthreads();
#pragma unroll
    for (int i = 0; i < 4; i++) {
        int n = outOff + n0 + ty + i * 8;
        float v = tb[tx][ty + i * 8];
        __nv_bfloat16 h = __float2bfloat16(v);
        float rem = v - __bfloat162float(h);
        hi[(size_t)n * K + k0 + tx] = h;
        lo[(size_t)n * K + k0 + tx] = __float2bfloat16(rem);
    }
}

__global__ __launch_bounds__(256) void convWT3(
    const float* __restrict__ W0, const float* __restrict__ W1,
    const float* __restrict__ W2, __nv_bfloat16* __restrict__ hi,
    __nv_bfloat16* __restrict__ lo)
{
    const float* W = (blockIdx.z == 0) ? W0 : (blockIdx.z == 1) ? W1 : W2;
    wt_body(W, hi, lo, E_DIM, HD, blockIdx.z * HD);
}

__global__ __launch_bounds__(256) void convWT(
    const float* __restrict__ W, __nv_bfloat16* __restrict__ hi,
    __nv_bfloat16* __restrict__ lo, int K, int N)
{
    wt_body(W, hi, lo, K, N, 0);
}

// ---------------------------------------------------------------------------
// Tensor-core block-sparse flash attention (split-bf16, 3-term), pipelined.
// 6 smem sections: Q,K,V x hi/lo; cp.async group discipline hides KV loads.
// Writes output directly as bf16 hi/lo.
// ---------------------------------------------------------------------------
#define APITCH 136
#define ASEC   (128 * APITCH)
#define AQH 0
#define AQL (1 * ASEC)
#define AKH (2 * ASEC)
#define AKL (3 * ASEC)
#define AVH (4 * ASEC)
#define AVL (5 * ASEC)
#define ATT_SMEM (6 * ASEC * 2)   // 208896 bytes

__global__ __launch_bounds__(256, 1) void attn_tc(
    const __nv_bfloat16* __restrict__ qkvh, const __nv_bfloat16* __restrict__ qkvl,
    const int* __restrict__ anchors,
    __nv_bfloat16* __restrict__ oh, __nv_bfloat16* __restrict__ ol)
{
    extern __shared__ __nv_bfloat16 asmem[];
    const uint32_t sb = smem_u32(asmem);
    const int t = blockIdx.x, h = blockIdx.y;
    const int tid = threadIdx.x, wid = tid >> 5, lane = tid & 31;
    const int g = lane >> 2, tq = lane & 3;
    const int lrow = lane & 15, lk2 = (lane >> 4) * 16;
    const int brow = (lane & 7) + ((lane >> 4) & 1) * 8;
    const int bk2 = ((lane >> 3) & 1) * 16;
    const int vm = lane >> 3, vr = lane & 7;
    const float sm_scale = 0.08838834764831845f;

    // tile list (duplicates preserved; anchors first, local last)
    int sels[K_ANCH + 1], nt = 0;
#pragma unroll
    for (int it = 0; it < K_ANCH; it++) {
        int s = anchors[(h * T_TILES + t) * K_ANCH + it];
        if (s <= t) sels[nt++] = s;
    }
    sels[nt++] = t;

    auto loadsec = [&](uint32_t sec, const __nv_bfloat16* src) {
#pragma unroll
        for (int i = tid; i < 2048; i += 256) {
            int row = i >> 4, ch = i & 15;
            cp16(sb + (sec + row * APITCH) * 2 + ch * 16, src + (size_t)row * NQKV + ch * 8);
        }
    };
    const size_t hoff = (size_t)h * D_HEAD;

    // prologue: group A = Q + K(0); group B = V(0)
    loadsec(AQH, qkvh + (size_t)(t * TILE) * NQKV + hoff);
    loadsec(AQL, qkvl + (size_t)(t * TILE) * NQKV + hoff);
    loadsec(AKH, qkvh + (size_t)(sels[0] * TILE) * NQKV + HD + hoff);
    loadsec(AKL, qkvl + (size_t)(sels[0] * TILE) * NQKV + HD + hoff);
    cp_commit();
    loadsec(AVH, qkvh + (size_t)(sels[0] * TILE) * NQKV + 2 * HD + hoff);
    loadsec(AVL, qkvl + (size_t)(sels[0] * TILE) * NQKV + 2 * HD + hoff);
    cp_commit();

    float o[16][4];
#pragma unroll
    for (int i = 0; i < 16; i++)
#pragma unroll
        for (int j = 0; j < 4; j++) o[i][j] = 0.f;
    float m0 = -INFINITY, m1 = -INFINITY, l0 = 0.f, l1 = 0.f;

    for (int jt = 0; jt < nt; jt++) {
        const int sel = sels[jt];

        cp_wait<1>();          // Q + K(jt) ready
        __syncthreads();

        // ---- S = Q K^T (3-term) ----
        float S[16][4];
#pragma unroll
        for (int i = 0; i < 16; i++)
#pragma unroll
            for (int j = 0; j < 4; j++) S[i][j] = 0.f;

#pragma unroll
        for (int ks = 0; ks < 8; ks++) {
            uint32_t ah[4], al[4];
            uint32_t ao = (uint32_t)((wid * 16 + lrow) * APITCH) * 2 + ks * 32 + lk2;
            ldm_x4(ah, sb + AQH * 2 + ao);
            ldm_x4(al, sb + AQL * 2 + ao);
#pragma unroll
            for (int p = 0; p < 8; p++) {
                uint32_t bb[4];
                uint32_t bo = (uint32_t)((p * 16 + brow) * APITCH) * 2 + ks * 32 + bk2;
                ldm_x4(bb, sb + AKH * 2 + bo);
                mma_bf16(S[2 * p],     ah, bb);
                mma_bf16(S[2 * p + 1], ah, bb + 2);
                mma_bf16(S[2 * p],     al, bb);
                mma_bf16(S[2 * p + 1], al, bb + 2);
                ldm_x4(bb, sb + AKL * 2 + bo);
                mma_bf16(S[2 * p],     ah, bb);
                mma_bf16(S[2 * p + 1], ah, bb + 2);
            }
        }
        __syncthreads();       // all warps done reading K sections

        // prefetch K(jt+1)
        if (jt + 1 < nt) {
            loadsec(AKH, qkvh + (size_t)(sels[jt + 1] * TILE) * NQKV + HD + hoff);
            loadsec(AKL, qkvl + (size_t)(sels[jt + 1] * TILE) * NQKV + HD + hoff);
        }
        cp_commit();

        // ---- online softmax (registers) ----
        const bool diag = (sel == t);
        const int qr0 = wid * 16 + g;
        float mx0 = -INFINITY, mx1 = -INFINITY;
#pragma unroll
        for (int nb = 0; nb < 16; nb++) {
            int c0 = nb * 8 + tq * 2, c1 = c0 + 1;
            float v0 = S[nb][0] * sm_scale, v1 = S[nb][1] * sm_scale;
            float v2 = S[nb][2] * sm_scale, v3 = S[nb][3] * sm_scale;
            if (diag) {
                if (c0 > qr0) v0 = -INFINITY;
                if (c1 > qr0) v1 = -INFINITY;
                if (c0 > qr0 + 8) v2 = -INFINITY;
                if (c1 > qr0 + 8) v3 = -INFINITY;
            }
            S[nb][0] = v0; S[nb][1] = v1; S[nb][2] = v2; S[nb][3] = v3;
            mx0 = fmaxf(mx0, fmaxf(v0, v1));
            mx1 = fmaxf(mx1, fmaxf(v2, v3));
        }
        mx0 = fmaxf(mx0, __shfl_xor_sync(0xffffffffu, mx0, 1));
        mx0 = fmaxf(mx0, __shfl_xor_sync(0xffffffffu, mx0, 2));
        mx1 = fmaxf(mx1, __shfl_xor_sync(0xffffffffu, mx1, 1));
        mx1 = fmaxf(mx1, __shfl_xor_sync(0xffffffffu, mx1, 2));

        float mn0 = fmaxf(m0, mx0), mn1 = fmaxf(m1, mx1);
        float fs0 = __expf(m0 - mn0), fs1 = __expf(m1 - mn1);
        m0 = mn0; m1 = mn1;

        float rs0 = 0.f, rs1 = 0.f;
#pragma unroll
        for (int nb = 0; nb < 16; nb++) {
            float p0 = __expf(S[nb][0] - mn0);
            float p1 = __expf(S[nb][1] - mn0);
            float p2 = __expf(S[nb][2] - mn1);
            float p3 = __expf(S[nb][3] - mn1);
            S[nb][0] = p0; S[nb][1] = p1; S[nb][2] = p2; S[nb][3] = p3;
            rs0 += p0 + p1; rs1 += p2 + p3;
        }
        rs0 += __shfl_xor_sync(0xffffffffu, rs0, 1);
        rs0 += __shfl_xor_sync(0xffffffffu, rs0, 2);
        rs1 += __shfl_xor_sync(0xffffffffu, rs1, 1);
        rs1 += __shfl_xor_sync(0xffffffffu, rs1, 2);
        l0 = l0 * fs0 + rs0;
        l1 = l1 * fs1 + rs1;
#pragma unroll
        for (int nb = 0; nb < 16; nb++) {
            o[nb][0] *= fs0; o[nb][1] *= fs0;
            o[nb][2] *= fs1; o[nb][3] *= fs1;
        }

        cp_wait<1>();          // V(jt) ready (K(jt+1) may remain in flight)
        __syncthreads();

        // ---- O += P V (3-term) ----
#pragma unroll
        for (int j = 0; j < 8; j++) {
            uint32_t ph[4], pl[4];
            float p00 = S[2 * j][0],     p01 = S[2 * j][1];
            float p10 = S[2 * j][2],     p11 = S[2 * j][3];
            float q00 = S[2 * j + 1][0], q01 = S[2 * j + 1][1];
            float q10 = S[2 * j + 1][2], q11 = S[2 * j + 1][3];
            ph[0] = pack_bf16(p00, p01);
            ph[1] = pack_bf16(p10, p11);
            ph[2] = pack_bf16(q00, q01);
            ph[3] = pack_bf16(q10, q11);
            pl[0] = pack_bf16(p00 - __uint_as_float(ph[0] << 16),
                              p01 - __uint_as_float(ph[0] & 0xffff0000u));
            pl[1] = pack_bf16(p10 - __uint_as_float(ph[1] << 16),
                              p11 - __uint_as_float(ph[1] & 0xffff0000u));
            pl[2] = pack_bf16(q00 - __uint_as_float(ph[2] << 16),
                              q01 - __uint_as_float(ph[2] & 0xffff0000u));
            pl[3] = pack_bf16(q10 - __uint_as_float(ph[3] << 16),
                              q11 - __uint_as_float(ph[3] & 0xffff0000u));

            uint32_t vrow = (uint32_t)(j * 16 + (vm & 1) * 8 + vr) * APITCH * 2;
#pragma unroll
            for (int p = 0; p < 8; p++) {
                uint32_t vb[4];
                uint32_t vo = vrow + (uint32_t)(p * 32 + (vm >> 1) * 16);
                ldm_x4_t(vb, sb + AVH * 2 + vo);
                mma_bf16(o[2 * p],     ph, vb);
                mma_bf16(o[2 * p + 1], ph, vb + 2);
                mma_bf16(o[2 * p],     pl, vb);
                mma_bf16(o[2 * p + 1], pl, vb + 2);
                ldm_x4_t(vb, sb + AVL * 2 + vo);
                mma_bf16(o[2 * p],     ph, vb);
                mma_bf16(o[2 * p + 1], ph, vb + 2);
            }
        }
        __syncthreads();       // all warps done reading V sections

        // prefetch V(jt+1)
        if (jt + 1 < nt) {
            loadsec(AVH, qkvh + (size_t)(sels[jt + 1] * TILE) * NQKV + 2 * HD + hoff);
            loadsec(AVL, qkvl + (size_t)(sels[jt + 1] * TILE) * NQKV + 2 * HD + hoff);
        }
        cp_commit();
    }

    // ---- epilogue: write bf16 hi/lo directly ----
    float inv0 = 1.0f / l0, inv1 = 1.0f / l1;
    int row0 = t * TILE + wid * 16 + g;
#pragma unroll
    for (int nb = 0; nb < 16; nb++) {
        size_t i0 = (size_t)row0 * HD + h * D_HEAD + nb * 8 + tq * 2;
        size_t i1 = i0 + (size_t)8 * HD;
        float a0 = o[nb][0] * inv0, a1 = o[nb][1] * inv0;
        float b0 = o[nb][2] * inv1, b1 = o[nb][3] * inv1;
        uint32_t hw = pack_bf16(a0, a1);
        *(uint32_t*)(oh + i0) = hw;
        *(uint32_t*)(ol + i0) = pack_bf16(a0 - __uint_as_float(hw << 16),
                                          a1 - __uint_as_float(hw & 0xffff0000u));
        hw = pack_bf16(b0, b1);
        *(uint32_t*)(oh + i1) = hw;
        *(uint32_t*)(ol + i1) = pack_bf16(b0 - __uint_as_float(hw << 16),
                                          b1 - __uint_as_float(hw & 0xffff0000u));
    }
}

// ---------------------------------------------------------------------------
// Launch
// ---------------------------------------------------------------------------
extern "C" void kernel_launch(void* const* d_in, const int* in_sizes, int n_in,
                              void* d_out, int out_size)
{
    (void)in_sizes; (void)n_in; (void)out_size;
    const float* x   = (const float*)d_in[0];
    const float* wq  = (const float*)d_in[1];
    const float* wk  = (const float*)d_in[2];
    const float* wv  = (const float*)d_in[3];
    const float* wo  = (const float*)d_in[4];
    const float* ang = (const float*)d_in[5];
    const int* anchors = (const int*)d_in[6];
    float* out = (float*)d_out;

    __nv_bfloat16 *qkvh, *qkvl, *xhi, *xlo, *ahi, *alo, *wth, *wtl, *woh, *wol;
    cudaGetSymbolAddress((void**)&qkvh, g_qkvh);
    cudaGetSymbolAddress((void**)&qkvl, g_qkvl);
    cudaGetSymbolAddress((void**)&xhi, g_xhi);
    cudaGetSymbolAddress((void**)&xlo, g_xlo);
    cudaGetSymbolAddress((void**)&ahi, g_ahi);
    cudaGetSymbolAddress((void**)&alo, g_alo);
    cudaGetSymbolAddress((void**)&wth, g_wt_hi);
    cudaGetSymbolAddress((void**)&wtl, g_wt_lo);
    cudaGetSymbolAddress((void**)&woh, g_wot_hi);
    cudaGetSymbolAddress((void**)&wol, g_wot_lo);

    cudaFuncSetAttribute(gemm_tc, cudaFuncAttributeMaxDynamicSharedMemorySize, GSMEM);
    cudaFuncSetAttribute(attn_tc, cudaFuncAttributeMaxDynamicSharedMemorySize, ATT_SMEM);

    // Split activations + transpose/split weights
    const int n4x = S_LEN * E_DIM / 4;
    conv_hilo<<<(n4x + 255) / 256, 256>>>(x, xhi, xlo, n4x);
    convWT3<<<dim3(HD / 32, E_DIM / 32, 3), dim3(32, 8)>>>(wq, wk, wv, wth, wtl);
    convWT<<<dim3(E_DIM / 32, HD / 32), dim3(32, 8)>>>(wo, woh, wol, HD, E_DIM);

    // Fused QKV projection with RoPE + hi/lo epilogue
    gemm_tc<<<dim3(NQKV / 128, S_LEN / 128), 128, GSMEM>>>(
        xhi, xlo, wth, wtl, nullptr, qkvh, qkvl, ang, S_LEN, NQKV, E_DIM, 1);

    // Tensor-core block-sparse flash attention (pipelined), bf16 hi/lo out
    attn_tc<<<dim3(T_TILES, H_NUM), 256, ATT_SMEM>>>(qkvh, qkvl, anchors, ahi, alo);

    // Output projection (fp32 epilogue to d_out)
    gemm_tc<<<dim3(E_DIM / 128, S_LEN / 128), 128, GSMEM>>>(
        ahi, alo, woh, wol, out, nullptr, nullptr, nullptr, S_LEN, E_DIM, HD, 0);
}